// round 1
// baseline (speedup 1.0000x reference)
#include <cuda_runtime.h>
#include <math.h>

#define NN   50000
#define EE0  800000
#define ETOT 850000
#define FH   128      // heads*hid for layers 0/1
#define NH   4
#define HC   32
#define FOUT 40

// ---------------- scratch (device globals; no allocation allowed) -------------
__device__ __align__(16) float g_feat[(size_t)NN * FH];   // layer input/output features
__device__ __align__(16) float g_h[(size_t)NN * FH];      // transformed features (h = x W^T)
__device__ __align__(16) float g_als[NN * NH];
__device__ __align__(16) float g_ald[NN * NH];
__device__ int g_deg[NN];
__device__ int g_row[NN + 1];
__device__ int g_cur[NN];
__device__ int g_srcv[ETOT];
__device__ int g_is64;

// ---------------- edge_index dtype detection ---------------------------------
// If the buffer is int64 (little endian, values < 2^31), every odd int32 word
// is zero. If it is int32, odd words are random node ids (~never zero).
__global__ void k_detect(const int* __restrict__ ei32) {
    __shared__ int zc;
    if (threadIdx.x == 0) zc = 0;
    __syncthreads();
    int z = 0;
    for (int k = threadIdx.x; k < 1024; k += blockDim.x)
        if (ei32[2 * k + 1] == 0) z++;
    atomicAdd(&zc, z);
    __syncthreads();
    if (threadIdx.x == 0) g_is64 = (zc > 512) ? 1 : 0;
}

__device__ __forceinline__ void get_edge(const void* ei, int e, int& s, int& d) {
    if (e >= EE0) { s = e - EE0; d = s; return; }
    if (g_is64) {
        const long long* p = (const long long*)ei;
        s = (int)p[e];
        d = (int)p[EE0 + e];
    } else {
        const int* p = (const int*)ei;
        s = p[e];
        d = p[EE0 + e];
    }
}

// ---------------- CSR build ---------------------------------------------------
__global__ void k_zero() {
    int i = blockIdx.x * blockDim.x + threadIdx.x;
    if (i < NN) g_deg[i] = 0;
}

__global__ void k_count(const void* __restrict__ ei) {
    int e = blockIdx.x * blockDim.x + threadIdx.x;
    if (e >= ETOT) return;
    int s, d;
    get_edge(ei, e, s, d);
    atomicAdd(&g_deg[d], 1);
}

__global__ void k_scan() {
    __shared__ int sums[1024];
    const int CH = (NN + 1023) / 1024;  // 49
    int t = threadIdx.x;
    int base = t * CH;
    int s = 0;
    for (int i = 0; i < CH; i++) {
        int idx = base + i;
        if (idx < NN) s += g_deg[idx];
    }
    sums[t] = s;
    __syncthreads();
    for (int off = 1; off < 1024; off <<= 1) {
        int v = (t >= off) ? sums[t - off] : 0;
        __syncthreads();
        sums[t] += v;
        __syncthreads();
    }
    int run = (t > 0) ? sums[t - 1] : 0;
    for (int i = 0; i < CH; i++) {
        int idx = base + i;
        if (idx < NN) {
            g_row[idx] = run;
            g_cur[idx] = run;
            run += g_deg[idx];
        }
    }
    if (t == 0) g_row[NN] = ETOT;
}

__global__ void k_fill(const void* __restrict__ ei) {
    int e = blockIdx.x * blockDim.x + threadIdx.x;
    if (e >= ETOT) return;
    int s, d;
    get_edge(ei, e, s, d);
    int pos = atomicAdd(&g_cur[d], 1);
    g_srcv[pos] = s;
}

// ---------------- GEMM h = X @ W^T (K=128, Nout=128) --------------------------
// Block: 256 threads, 64 rows x 128 cols. W fully staged in smem, transposed.
__global__ void __launch_bounds__(256, 2)
k_gemm128(const float* __restrict__ xin, int use_gfeat, const float* __restrict__ W) {
    extern __shared__ float sm[];
    float* Wt = sm;                 // [128][132]
    float* Xs = sm + 128 * 132;     // [64][128]
    const float* in = use_gfeat ? g_feat : xin;
    int t = threadIdx.x;
    int row0 = blockIdx.x * 64;

    for (int idx = t; idx < 128 * 128; idx += 256) {
        int c = idx >> 7, k = idx & 127;
        Wt[k * 132 + c] = W[idx];
    }
    for (int idx = t; idx < 64 * 32; idx += 256) {
        int r = idx >> 5, c4 = idx & 31;
        int row = row0 + r;
        float4 v = make_float4(0.f, 0.f, 0.f, 0.f);
        if (row < NN) v = *(const float4*)&in[(size_t)row * 128 + c4 * 4];
        *(float4*)&Xs[r * 128 + c4 * 4] = v;
    }
    __syncthreads();

    int cg = t & 15;   // col group: 8 cols
    int rg = t >> 4;   // row group: 4 rows
    float acc[4][8];
#pragma unroll
    for (int i = 0; i < 4; i++)
#pragma unroll
        for (int j = 0; j < 8; j++) acc[i][j] = 0.f;

#pragma unroll 8
    for (int k = 0; k < 128; k++) {
        float a[4];
#pragma unroll
        for (int i = 0; i < 4; i++) a[i] = Xs[(rg * 4 + i) * 128 + k];
        float4 b0 = *(float4*)&Wt[k * 132 + cg * 8];
        float4 b1 = *(float4*)&Wt[k * 132 + cg * 8 + 4];
        float bb[8] = {b0.x, b0.y, b0.z, b0.w, b1.x, b1.y, b1.z, b1.w};
#pragma unroll
        for (int i = 0; i < 4; i++)
#pragma unroll
            for (int j = 0; j < 8; j++) acc[i][j] = fmaf(a[i], bb[j], acc[i][j]);
    }

#pragma unroll
    for (int i = 0; i < 4; i++) {
        int row = row0 + rg * 4 + i;
        if (row < NN) {
            float4 v0 = make_float4(acc[i][0], acc[i][1], acc[i][2], acc[i][3]);
            float4 v1 = make_float4(acc[i][4], acc[i][5], acc[i][6], acc[i][7]);
            *(float4*)&g_h[(size_t)row * 128 + cg * 8] = v0;
            *(float4*)&g_h[(size_t)row * 128 + cg * 8 + 4] = v1;
        }
    }
}

// ---------------- attention dot products (layers 0/1: H=4, C=32) --------------
__global__ void k_att(const float* __restrict__ a_src, const float* __restrict__ a_dst) {
    int idx = blockIdx.x * blockDim.x + threadIdx.x;
    if (idx >= NN * NH) return;
    int n = idx >> 2, h = idx & 3;
    const float* hr = &g_h[(size_t)n * 128 + h * 32];
    const float* as = &a_src[h * 32];
    const float* ad = &a_dst[h * 32];
    float s = 0.f, d = 0.f;
#pragma unroll
    for (int i = 0; i < 32; i += 4) {
        float4 hv = *(const float4*)&hr[i];
        float4 av = *(const float4*)&as[i];
        float4 dv = *(const float4*)&ad[i];
        s += hv.x * av.x + hv.y * av.y + hv.z * av.z + hv.w * av.w;
        d += hv.x * dv.x + hv.y * dv.y + hv.z * dv.z + hv.w * dv.w;
    }
    g_als[idx] = s;
    g_ald[idx] = d;
}

// ---------------- per-dst softmax + aggregation (layers 0/1) -------------------
// One warp per destination node. Pass 1: online softmax stats per head.
// Pass 2: weighted gather of h[src] (float4 per lane = 128 cols per warp).
// Epilogue: +bias, ELU, write next-layer features.
__global__ void __launch_bounds__(256)
k_agg(const float* __restrict__ bias) {
    int warp = (blockIdx.x * blockDim.x + threadIdx.x) >> 5;
    int lane = threadIdx.x & 31;
    if (warp >= NN) return;
    int node = warp;
    int start = g_row[node], end = g_row[node + 1];

    float4 aldv = *(const float4*)&g_ald[node * 4];
    float ald[4] = {aldv.x, aldv.y, aldv.z, aldv.w};
    float m[4], dd[4];
#pragma unroll
    for (int h = 0; h < 4; h++) { m[h] = -1e30f; dd[h] = 0.f; }

    for (int j = start + lane; j < end; j += 32) {
        int s = g_srcv[j];
        float4 av = *(const float4*)&g_als[s * 4];
        float ev[4] = {av.x + ald[0], av.y + ald[1], av.z + ald[2], av.w + ald[3]};
#pragma unroll
        for (int h = 0; h < 4; h++) {
            float e = ev[h];
            e = (e >= 0.f) ? e : 0.2f * e;
            float M = fmaxf(m[h], e);
            dd[h] = dd[h] * __expf(m[h] - M) + __expf(e - M);
            m[h] = M;
        }
    }
#pragma unroll
    for (int off = 16; off > 0; off >>= 1) {
#pragma unroll
        for (int h = 0; h < 4; h++) {
            float mo = __shfl_xor_sync(0xffffffffu, m[h], off);
            float dn = __shfl_xor_sync(0xffffffffu, dd[h], off);
            float M = fmaxf(m[h], mo);
            dd[h] = dd[h] * __expf(m[h] - M) + dn * __expf(mo - M);
            m[h] = M;
        }
    }

    int head = lane >> 3;
    float mh = m[head];
    float invd = 1.f / dd[head];
    float aldh = ald[head];
    int c4 = lane * 4;
    float4 acc = make_float4(0.f, 0.f, 0.f, 0.f);

    for (int base = start; base < end; base += 32) {
        int j = base + lane;
        int sj = (j < end) ? g_srcv[j] : 0;
        int cnt = min(32, end - base);
        for (int t = 0; t < cnt; t++) {
            int s = __shfl_sync(0xffffffffu, sj, t);
            float e = __ldg(&g_als[s * 4 + head]) + aldh;
            e = (e >= 0.f) ? e : 0.2f * e;
            float alpha = __expf(e - mh) * invd;
            float4 hv = *(const float4*)&g_h[(size_t)s * 128 + c4];
            acc.x = fmaf(alpha, hv.x, acc.x);
            acc.y = fmaf(alpha, hv.y, acc.y);
            acc.z = fmaf(alpha, hv.z, acc.z);
            acc.w = fmaf(alpha, hv.w, acc.w);
        }
    }

    float4 bv = *(const float4*)&bias[c4];
    float r0 = acc.x + bv.x, r1 = acc.y + bv.y, r2 = acc.z + bv.z, r3 = acc.w + bv.w;
    r0 = (r0 > 0.f) ? r0 : expm1f(r0);
    r1 = (r1 > 0.f) ? r1 : expm1f(r1);
    r2 = (r2 > 0.f) ? r2 : expm1f(r2);
    r3 = (r3 > 0.f) ? r3 : expm1f(r3);
    *(float4*)&g_feat[(size_t)node * 128 + c4] = make_float4(r0, r1, r2, r3);
}

// ---------------- layer 2: GEMM h2 = feat @ W2^T (Nout=40) --------------------
__global__ void __launch_bounds__(256)
k_gemm40(const float* __restrict__ W2) {
    __shared__ float Wt[128 * 44];
    __shared__ float Xs[32 * 128];
    int t = threadIdx.x;
    int row0 = blockIdx.x * 32;

    for (int idx = t; idx < 40 * 128; idx += 256) {
        int c = idx >> 7, k = idx & 127;
        Wt[k * 44 + c] = W2[idx];
    }
    for (int idx = t; idx < 32 * 32; idx += 256) {
        int r = idx >> 5, c4 = idx & 31;
        int row = row0 + r;
        float4 v = make_float4(0.f, 0.f, 0.f, 0.f);
        if (row < NN) v = *(const float4*)&g_feat[(size_t)row * 128 + c4 * 4];
        *(float4*)&Xs[r * 128 + c4 * 4] = v;
    }
    __syncthreads();

    int cg = t & 7;    // 5 cols
    int rg = t >> 3;   // 1 row
    float acc[5] = {0.f, 0.f, 0.f, 0.f, 0.f};
#pragma unroll 4
    for (int k = 0; k < 128; k++) {
        float a = Xs[rg * 128 + k];
#pragma unroll
        for (int j = 0; j < 5; j++)
            acc[j] = fmaf(a, Wt[k * 44 + cg * 5 + j], acc[j]);
    }
    int row = row0 + rg;
    if (row < NN) {
#pragma unroll
        for (int j = 0; j < 5; j++)
            g_h[(size_t)row * 40 + cg * 5 + j] = acc[j];
    }
}

__global__ void k_att2(const float* __restrict__ a_src2, const float* __restrict__ a_dst2) {
    int n = blockIdx.x * blockDim.x + threadIdx.x;
    if (n >= NN) return;
    const float* hr = &g_h[(size_t)n * 40];
    float s = 0.f, d = 0.f;
#pragma unroll
    for (int i = 0; i < 40; i++) {
        float hv = hr[i];
        s = fmaf(hv, __ldg(&a_src2[i]), s);
        d = fmaf(hv, __ldg(&a_dst2[i]), d);
    }
    g_als[n] = s;
    g_ald[n] = d;
}

// ---------------- layer 2 aggregation + bias + log_softmax fused --------------
__global__ void __launch_bounds__(256)
k_agg2(const float* __restrict__ b2, float* __restrict__ out) {
    int warp = (blockIdx.x * blockDim.x + threadIdx.x) >> 5;
    int lane = threadIdx.x & 31;
    if (warp >= NN) return;
    int node = warp;
    int start = g_row[node], end = g_row[node + 1];
    float aldn = g_ald[node];

    float m = -1e30f, dd = 0.f;
    for (int j = start + lane; j < end; j += 32) {
        int s = g_srcv[j];
        float e = g_als[s] + aldn;
        e = (e >= 0.f) ? e : 0.2f * e;
        float M = fmaxf(m, e);
        dd = dd * __expf(m - M) + __expf(e - M);
        m = M;
    }
#pragma unroll
    for (int off = 16; off > 0; off >>= 1) {
        float mo = __shfl_xor_sync(0xffffffffu, m, off);
        float dn = __shfl_xor_sync(0xffffffffu, dd, off);
        float M = fmaxf(m, mo);
        dd = dd * __expf(m - M) + dn * __expf(mo - M);
        m = M;
    }
    float invd = 1.f / dd;

    float acc0 = 0.f, acc1 = 0.f;
    for (int base = start; base < end; base += 32) {
        int j = base + lane;
        int sj = (j < end) ? g_srcv[j] : 0;
        int cnt = min(32, end - base);
        for (int t = 0; t < cnt; t++) {
            int s = __shfl_sync(0xffffffffu, sj, t);
            float e = __ldg(&g_als[s]) + aldn;
            e = (e >= 0.f) ? e : 0.2f * e;
            float alpha = __expf(e - m) * invd;
            const float* hr = &g_h[(size_t)s * 40];
            acc0 = fmaf(alpha, hr[lane], acc0);
            if (lane < 8) acc1 = fmaf(alpha, hr[32 + lane], acc1);
        }
    }

    float v0 = acc0 + __ldg(&b2[lane]);
    float v1 = (lane < 8) ? (acc1 + __ldg(&b2[32 + lane])) : -1e30f;
    float mx = fmaxf(v0, v1);
#pragma unroll
    for (int off = 16; off > 0; off >>= 1)
        mx = fmaxf(mx, __shfl_xor_sync(0xffffffffu, mx, off));
    float se = __expf(v0 - mx) + ((lane < 8) ? __expf(v1 - mx) : 0.f);
#pragma unroll
    for (int off = 16; off > 0; off >>= 1)
        se += __shfl_xor_sync(0xffffffffu, se, off);
    float lse = mx + __logf(se);

    out[(size_t)node * 40 + lane] = v0 - lse;
    if (lane < 8) out[(size_t)node * 40 + 32 + lane] = v1 - lse;
}

// ---------------- launch -------------------------------------------------------
extern "C" void kernel_launch(void* const* d_in, const int* in_sizes, int n_in,
                              void* d_out, int out_size) {
    const float* x   = (const float*)d_in[0];
    const void*  ei  = d_in[1];
    const float* W0  = (const float*)d_in[2];
    const float* as0 = (const float*)d_in[3];
    const float* ad0 = (const float*)d_in[4];
    const float* b0  = (const float*)d_in[5];
    const float* W1  = (const float*)d_in[6];
    const float* as1 = (const float*)d_in[7];
    const float* ad1 = (const float*)d_in[8];
    const float* b1  = (const float*)d_in[9];
    const float* W2  = (const float*)d_in[10];
    const float* as2 = (const float*)d_in[11];
    const float* ad2 = (const float*)d_in[12];
    const float* b2  = (const float*)d_in[13];
    float* out = (float*)d_out;

    const int SMEM128 = (128 * 132 + 64 * 128) * (int)sizeof(float);  // 100352
    cudaFuncSetAttribute(k_gemm128, cudaFuncAttributeMaxDynamicSharedMemorySize, SMEM128);

    // CSR build (shared by all three layers)
    k_detect<<<1, 256>>>((const int*)ei);
    k_zero<<<(NN + 255) / 256, 256>>>();
    k_count<<<(ETOT + 255) / 256, 256>>>(ei);
    k_scan<<<1, 1024>>>();
    k_fill<<<(ETOT + 255) / 256, 256>>>(ei);

    const int GEMM_BLKS = (NN + 63) / 64;     // 782
    const int ATT_BLKS  = (NN * NH + 255) / 256;
    const int AGG_BLKS  = (NN * 32 + 255) / 256;  // one warp per node

    // layer 0
    k_gemm128<<<GEMM_BLKS, 256, SMEM128>>>(x, 0, W0);
    k_att<<<ATT_BLKS, 256>>>(as0, ad0);
    k_agg<<<AGG_BLKS, 256>>>(b0);

    // layer 1
    k_gemm128<<<GEMM_BLKS, 256, SMEM128>>>(nullptr, 1, W1);
    k_att<<<ATT_BLKS, 256>>>(as1, ad1);
    k_agg<<<AGG_BLKS, 256>>>(b1);

    // layer 2
    k_gemm40<<<(NN + 31) / 32, 256>>>(W2);
    k_att2<<<(NN + 255) / 256, 256>>>(as2, ad2);
    k_agg2<<<AGG_BLKS, 256>>>(b2, out);
}

// round 3
// speedup vs baseline: 1.2495x; 1.2495x over previous
#include <cuda_runtime.h>
#include <math.h>

#define NN   50000
#define EE0  800000
#define ETOT 850000
#define NH   4
#define SCAN_B 512
#define NB   ((NN + SCAN_B - 1) / SCAN_B)   // 98

// ---------------- scratch (device globals; no allocation allowed) -------------
__device__ __align__(16) float g_feat[(size_t)NN * 128];
__device__ __align__(16) float g_h[(size_t)NN * 128];
__device__ __align__(16) float g_als[NN * NH];
__device__ __align__(16) float g_ald[NN * NH];
__device__ int g_deg[NN];
__device__ int g_row[NN + 1];
__device__ int g_cur[NN];
__device__ int g_bsum[NB];
__device__ int g_boff[NB];
__device__ int g_srcv[ETOT];
__device__ int g_is64;

// ---------------- edge_index dtype detection ---------------------------------
__global__ void k_detect(const int* __restrict__ ei32) {
    __shared__ int zc;
    if (threadIdx.x == 0) zc = 0;
    __syncthreads();
    int z = 0;
    for (int k = threadIdx.x; k < 1024; k += blockDim.x)
        if (ei32[2 * k + 1] == 0) z++;
    atomicAdd(&zc, z);
    __syncthreads();
    if (threadIdx.x == 0) g_is64 = (zc > 512) ? 1 : 0;
}

__device__ __forceinline__ void get_edge(const void* ei, int e, int& s, int& d) {
    if (e >= EE0) { s = e - EE0; d = s; return; }
    if (g_is64) {
        const long long* p = (const long long*)ei;
        s = (int)p[e];
        d = (int)p[EE0 + e];
    } else {
        const int* p = (const int*)ei;
        s = p[e];
        d = p[EE0 + e];
    }
}

// ---------------- CSR build ---------------------------------------------------
__global__ void k_zero() {
    int i = blockIdx.x * blockDim.x + threadIdx.x;
    if (i < NN) g_deg[i] = 0;
}

__global__ void k_count(const void* __restrict__ ei) {
    int e = blockIdx.x * blockDim.x + threadIdx.x;
    if (e >= ETOT) return;
    int s, d;
    get_edge(ei, e, s, d);
    atomicAdd(&g_deg[d], 1);
}

// phase 1: per-block exclusive scan of g_deg into g_row, block totals to g_bsum
__global__ void k_scan1() {
    __shared__ int sm[SCAN_B];
    int t = threadIdx.x;
    int idx = blockIdx.x * SCAN_B + t;
    int v = (idx < NN) ? g_deg[idx] : 0;
    sm[t] = v;
    __syncthreads();
#pragma unroll
    for (int off = 1; off < SCAN_B; off <<= 1) {
        int p = (t >= off) ? sm[t - off] : 0;
        __syncthreads();
        sm[t] += p;
        __syncthreads();
    }
    if (idx < NN) g_row[idx] = sm[t] - v;        // exclusive within block
    if (t == SCAN_B - 1) g_bsum[blockIdx.x] = sm[t];
}

// phase 2: scan block totals (98 values) in one block
__global__ void k_scan2() {
    __shared__ int sm[128];
    int t = threadIdx.x;
    int v = (t < NB) ? g_bsum[t] : 0;
    sm[t] = v;
    __syncthreads();
#pragma unroll
    for (int off = 1; off < 128; off <<= 1) {
        int p = (t >= off) ? sm[t - off] : 0;
        __syncthreads();
        sm[t] += p;
        __syncthreads();
    }
    if (t < NB) g_boff[t] = sm[t] - v;           // exclusive
}

// phase 3: add block offsets, init g_cur, write sentinel
__global__ void k_scan3() {
    int idx = blockIdx.x * blockDim.x + threadIdx.x;
    if (idx < NN) {
        int r = g_row[idx] + g_boff[idx >> 9];
        g_row[idx] = r;
        g_cur[idx] = r;
    }
    if (idx == 0) g_row[NN] = ETOT;
}

__global__ void k_fill(const void* __restrict__ ei) {
    int e = blockIdx.x * blockDim.x + threadIdx.x;
    if (e >= ETOT) return;
    int s, d;
    get_edge(ei, e, s, d);
    int pos = atomicAdd(&g_cur[d], 1);
    g_srcv[pos] = s;
}

// ---------------- GEMM h = X @ W^T (K=128, Nout=128) + fused attention dots ---
__global__ void __launch_bounds__(256, 2)
k_gemm128(const float* __restrict__ xin, int use_gfeat, const float* __restrict__ W,
          const float* __restrict__ a_src, const float* __restrict__ a_dst) {
    extern __shared__ float sm[];
    float* Wt = sm;                 // [128][132]
    float* Xs = sm + 128 * 132;     // [64][128]
    const float* in = use_gfeat ? g_feat : xin;
    int t = threadIdx.x;
    int row0 = blockIdx.x * 64;

    for (int idx = t; idx < 128 * 128; idx += 256) {
        int c = idx >> 7, k = idx & 127;
        Wt[k * 132 + c] = W[idx];
    }
    for (int idx = t; idx < 64 * 32; idx += 256) {
        int r = idx >> 5, c4 = idx & 31;
        int row = row0 + r;
        float4 v = make_float4(0.f, 0.f, 0.f, 0.f);
        if (row < NN) v = *(const float4*)&in[(size_t)row * 128 + c4 * 4];
        *(float4*)&Xs[r * 128 + c4 * 4] = v;
    }

    int cg = t & 15;   // col group: 8 cols (cg*8 .. cg*8+7)
    int rg = t >> 4;   // row group: 4 rows
    // attention vectors for this thread's 8 columns (flat layout = head*32+c)
    float4 as0 = *(const float4*)&a_src[cg * 8];
    float4 as1 = *(const float4*)&a_src[cg * 8 + 4];
    float4 ad0 = *(const float4*)&a_dst[cg * 8];
    float4 ad1 = *(const float4*)&a_dst[cg * 8 + 4];
    __syncthreads();

    float acc[4][8];
#pragma unroll
    for (int i = 0; i < 4; i++)
#pragma unroll
        for (int j = 0; j < 8; j++) acc[i][j] = 0.f;

#pragma unroll 8
    for (int k = 0; k < 128; k++) {
        float a[4];
#pragma unroll
        for (int i = 0; i < 4; i++) a[i] = Xs[(rg * 4 + i) * 128 + k];
        float4 b0 = *(float4*)&Wt[k * 132 + cg * 8];
        float4 b1 = *(float4*)&Wt[k * 132 + cg * 8 + 4];
        float bb[8] = {b0.x, b0.y, b0.z, b0.w, b1.x, b1.y, b1.z, b1.w};
#pragma unroll
        for (int i = 0; i < 4; i++)
#pragma unroll
            for (int j = 0; j < 8; j++) acc[i][j] = fmaf(a[i], bb[j], acc[i][j]);
    }

    int head = cg >> 2;
#pragma unroll
    for (int i = 0; i < 4; i++) {
        int row = row0 + rg * 4 + i;
        // fused att dots: partial over this thread's 8 cols, reduce across 4 threads
        float ps = acc[i][0] * as0.x + acc[i][1] * as0.y + acc[i][2] * as0.z + acc[i][3] * as0.w
                 + acc[i][4] * as1.x + acc[i][5] * as1.y + acc[i][6] * as1.z + acc[i][7] * as1.w;
        float pd = acc[i][0] * ad0.x + acc[i][1] * ad0.y + acc[i][2] * ad0.z + acc[i][3] * ad0.w
                 + acc[i][4] * ad1.x + acc[i][5] * ad1.y + acc[i][6] * ad1.z + acc[i][7] * ad1.w;
        ps += __shfl_xor_sync(0xffffffffu, ps, 1);
        ps += __shfl_xor_sync(0xffffffffu, ps, 2);
        pd += __shfl_xor_sync(0xffffffffu, pd, 1);
        pd += __shfl_xor_sync(0xffffffffu, pd, 2);
        if (row < NN) {
            *(float4*)&g_h[(size_t)row * 128 + cg * 8] =
                make_float4(acc[i][0], acc[i][1], acc[i][2], acc[i][3]);
            *(float4*)&g_h[(size_t)row * 128 + cg * 8 + 4] =
                make_float4(acc[i][4], acc[i][5], acc[i][6], acc[i][7]);
            if ((cg & 3) == 0) {
                g_als[row * 4 + head] = ps;
                g_ald[row * 4 + head] = pd;
            }
        }
    }
}

// ---------------- per-dst softmax + aggregation (layers 0/1) -------------------
__global__ void __launch_bounds__(256)
k_agg(const float* __restrict__ bias) {
    int warp = (blockIdx.x * blockDim.x + threadIdx.x) >> 5;
    int lane = threadIdx.x & 31;
    if (warp >= NN) return;
    int node = warp;
    int start = g_row[node], end = g_row[node + 1];

    float4 aldv = *(const float4*)&g_ald[node * 4];
    float ald[4] = {aldv.x, aldv.y, aldv.z, aldv.w};
    float m[4], dd[4];
#pragma unroll
    for (int h = 0; h < 4; h++) { m[h] = -1e30f; dd[h] = 0.f; }

    for (int j = start + lane; j < end; j += 32) {
        int s = g_srcv[j];
        float4 av = *(const float4*)&g_als[s * 4];
        float ev[4] = {av.x + ald[0], av.y + ald[1], av.z + ald[2], av.w + ald[3]};
#pragma unroll
        for (int h = 0; h < 4; h++) {
            float e = ev[h];
            e = (e >= 0.f) ? e : 0.2f * e;
            float M = fmaxf(m[h], e);
            dd[h] = dd[h] * __expf(m[h] - M) + __expf(e - M);
            m[h] = M;
        }
    }
#pragma unroll
    for (int off = 16; off > 0; off >>= 1) {
#pragma unroll
        for (int h = 0; h < 4; h++) {
            float mo = __shfl_xor_sync(0xffffffffu, m[h], off);
            float dn = __shfl_xor_sync(0xffffffffu, dd[h], off);
            float M = fmaxf(m[h], mo);
            dd[h] = dd[h] * __expf(m[h] - M) + dn * __expf(mo - M);
            m[h] = M;
        }
    }

    int head = lane >> 3;
    int sub = lane & 7;
    float mh = m[head];
    float invd = 1.f / dd[head];
    float aldh = ald[head];
    int c4 = lane * 4;
    float4 acc = make_float4(0.f, 0.f, 0.f, 0.f);

    for (int base = start; base < end; base += 32) {
        int j = base + lane;
        int sj = (j < end) ? g_srcv[j] : 0;
        int cnt = min(32, end - base);
        // precompute alpha for edges base+sub+8k, for this lane's head
        float er[4];
#pragma unroll
        for (int k = 0; k < 4; k++) {
            int s2 = __shfl_sync(0xffffffffu, sj, sub + 8 * k);
            float e = __ldg(&g_als[s2 * 4 + head]) + aldh;
            e = (e >= 0.f) ? e : 0.2f * e;
            er[k] = __expf(e - mh) * invd;   // alpha (garbage lanes unused below)
        }
#pragma unroll 1
        for (int k8 = 0; k8 < 4; k8++) {
            int t0 = k8 * 8;
            if (t0 >= cnt) break;
            float ek = er[k8];
            int tmax = min(8, cnt - t0);
            for (int u = 0; u < tmax; u++) {
                int s = __shfl_sync(0xffffffffu, sj, t0 + u);
                float alpha = __shfl_sync(0xffffffffu, ek, (head << 3) | u);
                float4 hv = *(const float4*)&g_h[(size_t)s * 128 + c4];
                acc.x = fmaf(alpha, hv.x, acc.x);
                acc.y = fmaf(alpha, hv.y, acc.y);
                acc.z = fmaf(alpha, hv.z, acc.z);
                acc.w = fmaf(alpha, hv.w, acc.w);
            }
        }
    }

    float4 bv = *(const float4*)&bias[c4];
    float r0 = acc.x + bv.x, r1 = acc.y + bv.y, r2 = acc.z + bv.z, r3 = acc.w + bv.w;
    r0 = (r0 > 0.f) ? r0 : expm1f(r0);
    r1 = (r1 > 0.f) ? r1 : expm1f(r1);
    r2 = (r2 > 0.f) ? r2 : expm1f(r2);
    r3 = (r3 > 0.f) ? r3 : expm1f(r3);
    *(float4*)&g_feat[(size_t)node * 128 + c4] = make_float4(r0, r1, r2, r3);
}

// ---------------- layer 2: GEMM (Nout=40) + fused attention dots ---------------
__global__ void __launch_bounds__(256)
k_gemm40(const float* __restrict__ W2,
         const float* __restrict__ a_src2, const float* __restrict__ a_dst2) {
    __shared__ float Wt[128 * 44];
    __shared__ float Xs[32 * 128];
    int t = threadIdx.x;
    int row0 = blockIdx.x * 32;

    for (int idx = t; idx < 40 * 128; idx += 256) {
        int c = idx >> 7, k = idx & 127;
        Wt[k * 44 + c] = W2[idx];
    }
    for (int idx = t; idx < 32 * 32; idx += 256) {
        int r = idx >> 5, c4 = idx & 31;
        int row = row0 + r;
        float4 v = make_float4(0.f, 0.f, 0.f, 0.f);
        if (row < NN) v = *(const float4*)&g_feat[(size_t)row * 128 + c4 * 4];
        *(float4*)&Xs[r * 128 + c4 * 4] = v;
    }

    int cg = t & 7;    // 5 cols
    int rg = t >> 3;   // 1 row
    float as[5], ad[5];
#pragma unroll
    for (int j = 0; j < 5; j++) {
        as[j] = __ldg(&a_src2[cg * 5 + j]);
        ad[j] = __ldg(&a_dst2[cg * 5 + j]);
    }
    __syncthreads();

    float acc[5] = {0.f, 0.f, 0.f, 0.f, 0.f};
#pragma unroll 4
    for (int k = 0; k < 128; k++) {
        float a = Xs[rg * 128 + k];
#pragma unroll
        for (int j = 0; j < 5; j++)
            acc[j] = fmaf(a, Wt[k * 44 + cg * 5 + j], acc[j]);
    }

    float ps = 0.f, pd = 0.f;
#pragma unroll
    for (int j = 0; j < 5; j++) {
        ps = fmaf(acc[j], as[j], ps);
        pd = fmaf(acc[j], ad[j], pd);
    }
    ps += __shfl_xor_sync(0xffffffffu, ps, 1);
    ps += __shfl_xor_sync(0xffffffffu, ps, 2);
    ps += __shfl_xor_sync(0xffffffffu, ps, 4);
    pd += __shfl_xor_sync(0xffffffffu, pd, 1);
    pd += __shfl_xor_sync(0xffffffffu, pd, 2);
    pd += __shfl_xor_sync(0xffffffffu, pd, 4);

    int row = row0 + rg;
    if (row < NN) {
#pragma unroll
        for (int j = 0; j < 5; j++)
            g_h[(size_t)row * 40 + cg * 5 + j] = acc[j];
        if (cg == 0) {
            g_als[row] = ps;
            g_ald[row] = pd;
        }
    }
}

// ---------------- layer 2 aggregation + bias + log_softmax fused --------------
__global__ void __launch_bounds__(256)
k_agg2(const float* __restrict__ b2, float* __restrict__ out) {
    int warp = (blockIdx.x * blockDim.x + threadIdx.x) >> 5;
    int lane = threadIdx.x & 31;
    if (warp >= NN) return;
    int node = warp;
    int start = g_row[node], end = g_row[node + 1];
    float aldn = g_ald[node];

    float m = -1e30f, dd = 0.f;
    for (int j = start + lane; j < end; j += 32) {
        int s = g_srcv[j];
        float e = g_als[s] + aldn;
        e = (e >= 0.f) ? e : 0.2f * e;
        float M = fmaxf(m, e);
        dd = dd * __expf(m - M) + __expf(e - M);
        m = M;
    }
#pragma unroll
    for (int off = 16; off > 0; off >>= 1) {
        float mo = __shfl_xor_sync(0xffffffffu, m, off);
        float dn = __shfl_xor_sync(0xffffffffu, dd, off);
        float M = fmaxf(m, mo);
        dd = dd * __expf(m - M) + dn * __expf(mo - M);
        m = M;
    }
    float invd = 1.f / dd;

    float acc0 = 0.f, acc1 = 0.f;
    for (int base = start; base < end; base += 32) {
        int j = base + lane;
        int sj = (j < end) ? g_srcv[j] : 0;
        int cnt = min(32, end - base);
        float e = __ldg(&g_als[sj]) + aldn;
        e = (e >= 0.f) ? e : 0.2f * e;
        float al = __expf(e - m) * invd;     // alpha for this lane's edge
        for (int t = 0; t < cnt; t++) {
            int s = __shfl_sync(0xffffffffu, sj, t);
            float alpha = __shfl_sync(0xffffffffu, al, t);
            const float* hr = &g_h[(size_t)s * 40];
            acc0 = fmaf(alpha, hr[lane], acc0);
            if (lane < 8) acc1 = fmaf(alpha, hr[32 + lane], acc1);
        }
    }

    float v0 = acc0 + __ldg(&b2[lane]);
    float v1 = (lane < 8) ? (acc1 + __ldg(&b2[32 + lane])) : -1e30f;
    float mx = fmaxf(v0, v1);
#pragma unroll
    for (int off = 16; off > 0; off >>= 1)
        mx = fmaxf(mx, __shfl_xor_sync(0xffffffffu, mx, off));
    float se = __expf(v0 - mx) + ((lane < 8) ? __expf(v1 - mx) : 0.f);
#pragma unroll
    for (int off = 16; off > 0; off >>= 1)
        se += __shfl_xor_sync(0xffffffffu, se, off);
    float lse = mx + __logf(se);

    out[(size_t)node * 40 + lane] = v0 - lse;
    if (lane < 8) out[(size_t)node * 40 + 32 + lane] = v1 - lse;
}

// ---------------- launch -------------------------------------------------------
extern "C" void kernel_launch(void* const* d_in, const int* in_sizes, int n_in,
                              void* d_out, int out_size) {
    const float* x   = (const float*)d_in[0];
    const void*  ei  = d_in[1];
    const float* W0  = (const float*)d_in[2];
    const float* as0 = (const float*)d_in[3];
    const float* ad0 = (const float*)d_in[4];
    const float* b0  = (const float*)d_in[5];
    const float* W1  = (const float*)d_in[6];
    const float* as1 = (const float*)d_in[7];
    const float* ad1 = (const float*)d_in[8];
    const float* b1  = (const float*)d_in[9];
    const float* W2  = (const float*)d_in[10];
    const float* as2 = (const float*)d_in[11];
    const float* ad2 = (const float*)d_in[12];
    const float* b2  = (const float*)d_in[13];
    float* out = (float*)d_out;

    const int SMEM128 = (128 * 132 + 64 * 128) * (int)sizeof(float);  // 100352
    cudaFuncSetAttribute(k_gemm128, cudaFuncAttributeMaxDynamicSharedMemorySize, SMEM128);

    // CSR build
    k_detect<<<1, 256>>>((const int*)ei);
    k_zero<<<(NN + 511) / 512, 512>>>();
    k_count<<<(ETOT + 511) / 512, 512>>>(ei);
    k_scan1<<<NB, SCAN_B>>>();
    k_scan2<<<1, 128>>>();
    k_scan3<<<(NN + 511) / 512, 512>>>();
    k_fill<<<(ETOT + 511) / 512, 512>>>(ei);

    const int GEMM_BLKS = (NN + 63) / 64;         // 782
    const int AGG_BLKS  = (NN * 32 + 255) / 256;  // one warp per node

    // layer 0
    k_gemm128<<<GEMM_BLKS, 256, SMEM128>>>(x, 0, W0, as0, ad0);
    k_agg<<<AGG_BLKS, 256>>>(b0);

    // layer 1
    k_gemm128<<<GEMM_BLKS, 256, SMEM128>>>(nullptr, 1, W1, as1, ad1);
    k_agg<<<AGG_BLKS, 256>>>(b1);

    // layer 2
    k_gemm40<<<(NN + 31) / 32, 256>>>(W2, as2, ad2);
    k_agg2<<<AGG_BLKS, 256>>>(b2, out);
}

// round 4
// speedup vs baseline: 1.3511x; 1.0813x over previous
#include <cuda_runtime.h>
#include <math.h>

#define NN   50000
#define EE0  800000
#define ETOT 850000
#define NH   4
#define SCAN_B 512
#define NB   ((NN + SCAN_B - 1) / SCAN_B)   // 98

// ---------------- scratch (device globals; no allocation allowed) -------------
__device__ __align__(16) float g_feat[(size_t)NN * 128];
__device__ __align__(16) float g_h[(size_t)NN * 128];
__device__ __align__(16) float g_als[NN * NH];
__device__ __align__(16) float g_ald[NN * NH];
__device__ int g_deg[NN];
__device__ int g_row[NN + 1];
__device__ int g_cur[NN];
__device__ int g_bsum[NB];
__device__ int g_boff[NB];
__device__ int g_srcv[ETOT];
__device__ int g_is64;

// ---------------- edge_index dtype detection ---------------------------------
__global__ void k_detect(const int* __restrict__ ei32) {
    __shared__ int zc;
    if (threadIdx.x == 0) zc = 0;
    __syncthreads();
    int z = 0;
    for (int k = threadIdx.x; k < 1024; k += blockDim.x)
        if (ei32[2 * k + 1] == 0) z++;
    atomicAdd(&zc, z);
    __syncthreads();
    if (threadIdx.x == 0) g_is64 = (zc > 512) ? 1 : 0;
}

__device__ __forceinline__ void get_edge(const void* ei, int e, int& s, int& d) {
    if (e >= EE0) { s = e - EE0; d = s; return; }
    if (g_is64) {
        const long long* p = (const long long*)ei;
        s = (int)p[e];
        d = (int)p[EE0 + e];
    } else {
        const int* p = (const int*)ei;
        s = p[e];
        d = p[EE0 + e];
    }
}

__device__ __forceinline__ int get_dst(const void* ei, int e) {
    if (e >= EE0) return e - EE0;
    if (g_is64) return (int)((const long long*)ei)[EE0 + e];
    return ((const int*)ei)[EE0 + e];
}

// ---------------- CSR build ---------------------------------------------------
__global__ void k_zero() {
    int i = blockIdx.x * blockDim.x + threadIdx.x;
    if (i < NN) g_deg[i] = 0;
}

__global__ void k_count(const void* __restrict__ ei) {
    int e = blockIdx.x * blockDim.x + threadIdx.x;
    if (e >= ETOT) return;
    atomicAdd(&g_deg[get_dst(ei, e)], 1);
}

// phase 1: per-block exclusive scan of g_deg into g_row, block totals to g_bsum
__global__ void k_scan1() {
    __shared__ int sm[SCAN_B];
    int t = threadIdx.x;
    int idx = blockIdx.x * SCAN_B + t;
    int v = (idx < NN) ? g_deg[idx] : 0;
    sm[t] = v;
    __syncthreads();
#pragma unroll
    for (int off = 1; off < SCAN_B; off <<= 1) {
        int p = (t >= off) ? sm[t - off] : 0;
        __syncthreads();
        sm[t] += p;
        __syncthreads();
    }
    if (idx < NN) g_row[idx] = sm[t] - v;        // exclusive within block
    if (t == SCAN_B - 1) g_bsum[blockIdx.x] = sm[t];
}

// phase 2: scan block totals (98 values) in one block
__global__ void k_scan2() {
    __shared__ int sm[128];
    int t = threadIdx.x;
    int v = (t < NB) ? g_bsum[t] : 0;
    sm[t] = v;
    __syncthreads();
#pragma unroll
    for (int off = 1; off < 128; off <<= 1) {
        int p = (t >= off) ? sm[t - off] : 0;
        __syncthreads();
        sm[t] += p;
        __syncthreads();
    }
    if (t < NB) g_boff[t] = sm[t] - v;           // exclusive
}

// phase 3: add block offsets, init g_cur, write sentinel
__global__ void k_scan3() {
    int idx = blockIdx.x * blockDim.x + threadIdx.x;
    if (idx < NN) {
        int r = g_row[idx] + g_boff[idx >> 9];
        g_row[idx] = r;
        g_cur[idx] = r;
    }
    if (idx == 0) g_row[NN] = ETOT;
}

__global__ void k_fill(const void* __restrict__ ei) {
    int e = blockIdx.x * blockDim.x + threadIdx.x;
    if (e >= ETOT) return;
    int s, d;
    get_edge(ei, e, s, d);
    int pos = atomicAdd(&g_cur[d], 1);
    g_srcv[pos] = s;
}

// ---------------- GEMM h = X @ W^T (K=128, Nout=128) + fused attention dots ---
__global__ void __launch_bounds__(256, 2)
k_gemm128(const float* __restrict__ xin, int use_gfeat, const float* __restrict__ W,
          const float* __restrict__ a_src, const float* __restrict__ a_dst) {
    extern __shared__ float sm[];
    float* Wt = sm;                 // [128][132]
    float* Xs = sm + 128 * 132;     // [64][128]
    const float* in = use_gfeat ? g_feat : xin;
    int t = threadIdx.x;
    int row0 = blockIdx.x * 64;

    for (int idx = t; idx < 128 * 128; idx += 256) {
        int c = idx >> 7, k = idx & 127;
        Wt[k * 132 + c] = W[idx];
    }
    for (int idx = t; idx < 64 * 32; idx += 256) {
        int r = idx >> 5, c4 = idx & 31;
        int row = row0 + r;
        float4 v = make_float4(0.f, 0.f, 0.f, 0.f);
        if (row < NN) v = *(const float4*)&in[(size_t)row * 128 + c4 * 4];
        *(float4*)&Xs[r * 128 + c4 * 4] = v;
    }

    int cg = t & 15;   // col group: 8 cols
    int rg = t >> 4;   // row group: 4 rows
    float4 as0 = *(const float4*)&a_src[cg * 8];
    float4 as1 = *(const float4*)&a_src[cg * 8 + 4];
    float4 ad0 = *(const float4*)&a_dst[cg * 8];
    float4 ad1 = *(const float4*)&a_dst[cg * 8 + 4];
    __syncthreads();

    float acc[4][8];
#pragma unroll
    for (int i = 0; i < 4; i++)
#pragma unroll
        for (int j = 0; j < 8; j++) acc[i][j] = 0.f;

#pragma unroll 8
    for (int k = 0; k < 128; k++) {
        float a[4];
#pragma unroll
        for (int i = 0; i < 4; i++) a[i] = Xs[(rg * 4 + i) * 128 + k];
        float4 b0 = *(float4*)&Wt[k * 132 + cg * 8];
        float4 b1 = *(float4*)&Wt[k * 132 + cg * 8 + 4];
        float bb[8] = {b0.x, b0.y, b0.z, b0.w, b1.x, b1.y, b1.z, b1.w};
#pragma unroll
        for (int i = 0; i < 4; i++)
#pragma unroll
            for (int j = 0; j < 8; j++) acc[i][j] = fmaf(a[i], bb[j], acc[i][j]);
    }

    int head = cg >> 2;
#pragma unroll
    for (int i = 0; i < 4; i++) {
        int row = row0 + rg * 4 + i;
        float ps = acc[i][0] * as0.x + acc[i][1] * as0.y + acc[i][2] * as0.z + acc[i][3] * as0.w
                 + acc[i][4] * as1.x + acc[i][5] * as1.y + acc[i][6] * as1.z + acc[i][7] * as1.w;
        float pd = acc[i][0] * ad0.x + acc[i][1] * ad0.y + acc[i][2] * ad0.z + acc[i][3] * ad0.w
                 + acc[i][4] * ad1.x + acc[i][5] * ad1.y + acc[i][6] * ad1.z + acc[i][7] * ad1.w;
        ps += __shfl_xor_sync(0xffffffffu, ps, 1);
        ps += __shfl_xor_sync(0xffffffffu, ps, 2);
        pd += __shfl_xor_sync(0xffffffffu, pd, 1);
        pd += __shfl_xor_sync(0xffffffffu, pd, 2);
        if (row < NN) {
            *(float4*)&g_h[(size_t)row * 128 + cg * 8] =
                make_float4(acc[i][0], acc[i][1], acc[i][2], acc[i][3]);
            *(float4*)&g_h[(size_t)row * 128 + cg * 8 + 4] =
                make_float4(acc[i][4], acc[i][5], acc[i][6], acc[i][7]);
            if ((cg & 3) == 0) {
                g_als[row * 4 + head] = ps;
                g_ald[row * 4 + head] = pd;
            }
        }
    }
}

// ---------------- single-pass max-free softmax + aggregation (layers 0/1) -----
// One warp per dst node. alpha_e = exp(leaky(e)) accumulated directly; the den
// accumulates the identical broadcast sequence in every lane of a head, so
// acc/den matches the reference softmax exactly (e bounded ~|15| << 88).
__global__ void __launch_bounds__(256)
k_agg(const float* __restrict__ bias) {
    int warp = (blockIdx.x * blockDim.x + threadIdx.x) >> 5;
    int lane = threadIdx.x & 31;
    if (warp >= NN) return;
    int node = warp;
    int start = g_row[node], end = g_row[node + 1];

    int head = lane >> 3;
    int sub = lane & 7;
    float aldh = g_ald[node * 4 + head];
    int c4 = lane * 4;
    float4 acc = make_float4(0.f, 0.f, 0.f, 0.f);
    float den = 0.f;

    for (int base = start; base < end; base += 32) {
        int j = base + lane;
        int sj = (j < end) ? g_srcv[j] : 0;
        int cnt = min(32, end - base);
        // lane (head, sub) computes exp-weight for edges base+sub+8k under its head
        float er[4];
#pragma unroll
        for (int k = 0; k < 4; k++) {
            int s2 = __shfl_sync(0xffffffffu, sj, sub + 8 * k);
            float e = __ldg(&g_als[s2 * 4 + head]) + aldh;
            e = (e >= 0.f) ? e : 0.2f * e;
            er[k] = __expf(e);     // unused lanes (>= cnt) produce finite garbage
        }
#pragma unroll 1
        for (int k8 = 0; k8 < 4; k8++) {
            int t0 = k8 * 8;
            if (t0 >= cnt) break;
            float ek = er[k8];
            int tmax = min(8, cnt - t0);
            for (int u = 0; u < tmax; u++) {
                int s = __shfl_sync(0xffffffffu, sj, t0 + u);
                float w = __shfl_sync(0xffffffffu, ek, (head << 3) | u);
                float4 hv = *(const float4*)&g_h[(size_t)s * 128 + c4];
                den += w;
                acc.x = fmaf(w, hv.x, acc.x);
                acc.y = fmaf(w, hv.y, acc.y);
                acc.z = fmaf(w, hv.z, acc.z);
                acc.w = fmaf(w, hv.w, acc.w);
            }
        }
    }

    float invd = 1.f / den;
    float4 bv = *(const float4*)&bias[c4];
    float r0 = fmaf(acc.x, invd, bv.x);
    float r1 = fmaf(acc.y, invd, bv.y);
    float r2 = fmaf(acc.z, invd, bv.z);
    float r3 = fmaf(acc.w, invd, bv.w);
    r0 = (r0 > 0.f) ? r0 : expm1f(r0);
    r1 = (r1 > 0.f) ? r1 : expm1f(r1);
    r2 = (r2 > 0.f) ? r2 : expm1f(r2);
    r3 = (r3 > 0.f) ? r3 : expm1f(r3);
    *(float4*)&g_feat[(size_t)node * 128 + c4] = make_float4(r0, r1, r2, r3);
}

// ---------------- layer 2: GEMM (Nout=40) + fused attention dots ---------------
__global__ void __launch_bounds__(256)
k_gemm40(const float* __restrict__ W2,
         const float* __restrict__ a_src2, const float* __restrict__ a_dst2) {
    __shared__ float Wt[128 * 44];
    __shared__ float Xs[32 * 128];
    int t = threadIdx.x;
    int row0 = blockIdx.x * 32;

    for (int idx = t; idx < 40 * 128; idx += 256) {
        int c = idx >> 7, k = idx & 127;
        Wt[k * 44 + c] = W2[idx];
    }
    for (int idx = t; idx < 32 * 32; idx += 256) {
        int r = idx >> 5, c4 = idx & 31;
        int row = row0 + r;
        float4 v = make_float4(0.f, 0.f, 0.f, 0.f);
        if (row < NN) v = *(const float4*)&g_feat[(size_t)row * 128 + c4 * 4];
        *(float4*)&Xs[r * 128 + c4 * 4] = v;
    }

    int cg = t & 7;    // 5 cols
    int rg = t >> 3;   // 1 row
    float as[5], ad[5];
#pragma unroll
    for (int j = 0; j < 5; j++) {
        as[j] = __ldg(&a_src2[cg * 5 + j]);
        ad[j] = __ldg(&a_dst2[cg * 5 + j]);
    }
    __syncthreads();

    float acc[5] = {0.f, 0.f, 0.f, 0.f, 0.f};
#pragma unroll 4
    for (int k = 0; k < 128; k++) {
        float a = Xs[rg * 128 + k];
#pragma unroll
        for (int j = 0; j < 5; j++)
            acc[j] = fmaf(a, Wt[k * 44 + cg * 5 + j], acc[j]);
    }

    float ps = 0.f, pd = 0.f;
#pragma unroll
    for (int j = 0; j < 5; j++) {
        ps = fmaf(acc[j], as[j], ps);
        pd = fmaf(acc[j], ad[j], pd);
    }
    ps += __shfl_xor_sync(0xffffffffu, ps, 1);
    ps += __shfl_xor_sync(0xffffffffu, ps, 2);
    ps += __shfl_xor_sync(0xffffffffu, ps, 4);
    pd += __shfl_xor_sync(0xffffffffu, pd, 1);
    pd += __shfl_xor_sync(0xffffffffu, pd, 2);
    pd += __shfl_xor_sync(0xffffffffu, pd, 4);

    int row = row0 + rg;
    if (row < NN) {
#pragma unroll
        for (int j = 0; j < 5; j++)
            g_h[(size_t)row * 40 + cg * 5 + j] = acc[j];
        if (cg == 0) {
            g_als[row] = ps;
            g_ald[row] = pd;
        }
    }
}

// ------- layer 2: single-pass aggregation + bias + log_softmax fused ----------
__global__ void __launch_bounds__(256)
k_agg2(const float* __restrict__ b2, float* __restrict__ out) {
    int warp = (blockIdx.x * blockDim.x + threadIdx.x) >> 5;
    int lane = threadIdx.x & 31;
    if (warp >= NN) return;
    int node = warp;
    int start = g_row[node], end = g_row[node + 1];
    float aldn = g_ald[node];

    float acc0 = 0.f, acc1 = 0.f, den = 0.f;
    for (int base = start; base < end; base += 32) {
        int j = base + lane;
        int sj = (j < end) ? g_srcv[j] : 0;
        int cnt = min(32, end - base);
        float e = __ldg(&g_als[sj]) + aldn;
        e = (e >= 0.f) ? e : 0.2f * e;
        float al = __expf(e);                // exp-weight for this lane's edge
        for (int t = 0; t < cnt; t++) {
            int s = __shfl_sync(0xffffffffu, sj, t);
            float w = __shfl_sync(0xffffffffu, al, t);
            const float* hr = &g_h[(size_t)s * 40];
            den += w;
            acc0 = fmaf(w, hr[lane], acc0);
            if (lane < 8) acc1 = fmaf(w, hr[32 + lane], acc1);
        }
    }
    float invd = 1.f / den;

    float v0 = fmaf(acc0, invd, __ldg(&b2[lane]));
    float v1 = (lane < 8) ? fmaf(acc1, invd, __ldg(&b2[32 + lane])) : -1e30f;
    float mx = fmaxf(v0, v1);
#pragma unroll
    for (int off = 16; off > 0; off >>= 1)
        mx = fmaxf(mx, __shfl_xor_sync(0xffffffffu, mx, off));
    float se = __expf(v0 - mx) + ((lane < 8) ? __expf(v1 - mx) : 0.f);
#pragma unroll
    for (int off = 16; off > 0; off >>= 1)
        se += __shfl_xor_sync(0xffffffffu, se, off);
    float lse = mx + __logf(se);

    out[(size_t)node * 40 + lane] = v0 - lse;
    if (lane < 8) out[(size_t)node * 40 + 32 + lane] = v1 - lse;
}

// ---------------- launch -------------------------------------------------------
extern "C" void kernel_launch(void* const* d_in, const int* in_sizes, int n_in,
                              void* d_out, int out_size) {
    const float* x   = (const float*)d_in[0];
    const void*  ei  = d_in[1];
    const float* W0  = (const float*)d_in[2];
    const float* as0 = (const float*)d_in[3];
    const float* ad0 = (const float*)d_in[4];
    const float* b0  = (const float*)d_in[5];
    const float* W1  = (const float*)d_in[6];
    const float* as1 = (const float*)d_in[7];
    const float* ad1 = (const float*)d_in[8];
    const float* b1  = (const float*)d_in[9];
    const float* W2  = (const float*)d_in[10];
    const float* as2 = (const float*)d_in[11];
    const float* ad2 = (const float*)d_in[12];
    const float* b2  = (const float*)d_in[13];
    float* out = (float*)d_out;

    const int SMEM128 = (128 * 132 + 64 * 128) * (int)sizeof(float);  // 100352
    cudaFuncSetAttribute(k_gemm128, cudaFuncAttributeMaxDynamicSharedMemorySize, SMEM128);

    // CSR build
    k_detect<<<1, 256>>>((const int*)ei);
    k_zero<<<(NN + 511) / 512, 512>>>();
    k_count<<<(ETOT + 511) / 512, 512>>>(ei);
    k_scan1<<<NB, SCAN_B>>>();
    k_scan2<<<1, 128>>>();
    k_scan3<<<(NN + 511) / 512, 512>>>();
    k_fill<<<(ETOT + 511) / 512, 512>>>(ei);

    const int GEMM_BLKS = (NN + 63) / 64;         // 782
    const int AGG_BLKS  = (NN * 32 + 255) / 256;  // one warp per node

    // layer 0
    k_gemm128<<<GEMM_BLKS, 256, SMEM128>>>(x, 0, W0, as0, ad0);
    k_agg<<<AGG_BLKS, 256>>>(b0);

    // layer 1
    k_gemm128<<<GEMM_BLKS, 256, SMEM128>>>(nullptr, 1, W1, as1, ad1);
    k_agg<<<AGG_BLKS, 256>>>(b1);

    // layer 2
    k_gemm40<<<(NN + 31) / 32, 256>>>(W2, as2, ad2);
    k_agg2<<<AGG_BLKS, 256>>>(b2, out);
}

// round 5
// speedup vs baseline: 1.4239x; 1.0539x over previous
#include <cuda_runtime.h>
#include <math.h>

#define NN   50000
#define EE0  800000
#define ETOT 850000
#define NH   4
#define SCAN_B 512
#define NB   ((NN + SCAN_B - 1) / SCAN_B)   // 98

// ---------------- scratch (device globals; no allocation allowed) -------------
__device__ __align__(16) float g_feat[(size_t)NN * 128];
__device__ __align__(16) float g_h[(size_t)NN * 128];
__device__ __align__(16) float g_als[NN * NH];
__device__ __align__(16) float g_ald[NN * NH];
__device__ int g_deg[NN];
__device__ int g_row[NN + 1];
__device__ int g_cur[NN];
__device__ int g_bsum[NB];
__device__ int g_boff[NB];
__device__ int g_srcv[ETOT];
__device__ int g_is64;

// ---------------- edge_index dtype detection ---------------------------------
__global__ void k_detect(const int* __restrict__ ei32) {
    __shared__ int zc;
    if (threadIdx.x == 0) zc = 0;
    __syncthreads();
    int z = 0;
    for (int k = threadIdx.x; k < 1024; k += blockDim.x)
        if (ei32[2 * k + 1] == 0) z++;
    atomicAdd(&zc, z);
    __syncthreads();
    if (threadIdx.x == 0) g_is64 = (zc > 512) ? 1 : 0;
}

__device__ __forceinline__ void get_edge(const void* ei, int e, int& s, int& d) {
    if (e >= EE0) { s = e - EE0; d = s; return; }
    if (g_is64) {
        const long long* p = (const long long*)ei;
        s = (int)p[e];
        d = (int)p[EE0 + e];
    } else {
        const int* p = (const int*)ei;
        s = p[e];
        d = p[EE0 + e];
    }
}

__device__ __forceinline__ int get_dst(const void* ei, int e) {
    if (e >= EE0) return e - EE0;
    if (g_is64) return (int)((const long long*)ei)[EE0 + e];
    return ((const int*)ei)[EE0 + e];
}

// ---------------- CSR build ---------------------------------------------------
__global__ void k_zero() {
    int i = blockIdx.x * blockDim.x + threadIdx.x;
    if (i < NN) g_deg[i] = 0;
}

__global__ void k_count(const void* __restrict__ ei) {
    int e = blockIdx.x * blockDim.x + threadIdx.x;
    if (e >= ETOT) return;
    atomicAdd(&g_deg[get_dst(ei, e)], 1);
}

__global__ void k_scan1() {
    __shared__ int sm[SCAN_B];
    int t = threadIdx.x;
    int idx = blockIdx.x * SCAN_B + t;
    int v = (idx < NN) ? g_deg[idx] : 0;
    sm[t] = v;
    __syncthreads();
#pragma unroll
    for (int off = 1; off < SCAN_B; off <<= 1) {
        int p = (t >= off) ? sm[t - off] : 0;
        __syncthreads();
        sm[t] += p;
        __syncthreads();
    }
    if (idx < NN) g_row[idx] = sm[t] - v;
    if (t == SCAN_B - 1) g_bsum[blockIdx.x] = sm[t];
}

__global__ void k_scan2() {
    __shared__ int sm[128];
    int t = threadIdx.x;
    int v = (t < NB) ? g_bsum[t] : 0;
    sm[t] = v;
    __syncthreads();
#pragma unroll
    for (int off = 1; off < 128; off <<= 1) {
        int p = (t >= off) ? sm[t - off] : 0;
        __syncthreads();
        sm[t] += p;
        __syncthreads();
    }
    if (t < NB) g_boff[t] = sm[t] - v;
}

__global__ void k_scan3() {
    int idx = blockIdx.x * blockDim.x + threadIdx.x;
    if (idx < NN) {
        int r = g_row[idx] + g_boff[idx >> 9];
        g_row[idx] = r;
        g_cur[idx] = r;
    }
    if (idx == 0) g_row[NN] = ETOT;
}

__global__ void k_fill(const void* __restrict__ ei) {
    int e = blockIdx.x * blockDim.x + threadIdx.x;
    if (e >= ETOT) return;
    int s, d;
    get_edge(ei, e, s, d);
    int pos = atomicAdd(&g_cur[d], 1);
    g_srcv[pos] = s;
}

// ---------------- GEMM h = X @ W^T (K=128, Nout=128) + fused attention dots ---
__global__ void __launch_bounds__(256, 2)
k_gemm128(const float* __restrict__ xin, int use_gfeat, const float* __restrict__ W,
          const float* __restrict__ a_src, const float* __restrict__ a_dst) {
    extern __shared__ float sm[];
    float* Wt = sm;                 // [128][132]
    float* Xs = sm + 128 * 132;     // [64][128]
    const float* in = use_gfeat ? g_feat : xin;
    int t = threadIdx.x;
    int row0 = blockIdx.x * 64;

    for (int idx = t; idx < 128 * 128; idx += 256) {
        int c = idx >> 7, k = idx & 127;
        Wt[k * 132 + c] = W[idx];
    }
    for (int idx = t; idx < 64 * 32; idx += 256) {
        int r = idx >> 5, c4 = idx & 31;
        int row = row0 + r;
        float4 v = make_float4(0.f, 0.f, 0.f, 0.f);
        if (row < NN) v = *(const float4*)&in[(size_t)row * 128 + c4 * 4];
        *(float4*)&Xs[r * 128 + c4 * 4] = v;
    }

    int cg = t & 15;
    int rg = t >> 4;
    float4 as0 = *(const float4*)&a_src[cg * 8];
    float4 as1 = *(const float4*)&a_src[cg * 8 + 4];
    float4 ad0 = *(const float4*)&a_dst[cg * 8];
    float4 ad1 = *(const float4*)&a_dst[cg * 8 + 4];
    __syncthreads();

    float acc[4][8];
#pragma unroll
    for (int i = 0; i < 4; i++)
#pragma unroll
        for (int j = 0; j < 8; j++) acc[i][j] = 0.f;

#pragma unroll 8
    for (int k = 0; k < 128; k++) {
        float a[4];
#pragma unroll
        for (int i = 0; i < 4; i++) a[i] = Xs[(rg * 4 + i) * 128 + k];
        float4 b0 = *(float4*)&Wt[k * 132 + cg * 8];
        float4 b1 = *(float4*)&Wt[k * 132 + cg * 8 + 4];
        float bb[8] = {b0.x, b0.y, b0.z, b0.w, b1.x, b1.y, b1.z, b1.w};
#pragma unroll
        for (int i = 0; i < 4; i++)
#pragma unroll
            for (int j = 0; j < 8; j++) acc[i][j] = fmaf(a[i], bb[j], acc[i][j]);
    }

    int head = cg >> 2;
#pragma unroll
    for (int i = 0; i < 4; i++) {
        int row = row0 + rg * 4 + i;
        float ps = acc[i][0] * as0.x + acc[i][1] * as0.y + acc[i][2] * as0.z + acc[i][3] * as0.w
                 + acc[i][4] * as1.x + acc[i][5] * as1.y + acc[i][6] * as1.z + acc[i][7] * as1.w;
        float pd = acc[i][0] * ad0.x + acc[i][1] * ad0.y + acc[i][2] * ad0.z + acc[i][3] * ad0.w
                 + acc[i][4] * ad1.x + acc[i][5] * ad1.y + acc[i][6] * ad1.z + acc[i][7] * ad1.w;
        ps += __shfl_xor_sync(0xffffffffu, ps, 1);
        ps += __shfl_xor_sync(0xffffffffu, ps, 2);
        pd += __shfl_xor_sync(0xffffffffu, pd, 1);
        pd += __shfl_xor_sync(0xffffffffu, pd, 2);
        if (row < NN) {
            *(float4*)&g_h[(size_t)row * 128 + cg * 8] =
                make_float4(acc[i][0], acc[i][1], acc[i][2], acc[i][3]);
            *(float4*)&g_h[(size_t)row * 128 + cg * 8 + 4] =
                make_float4(acc[i][4], acc[i][5], acc[i][6], acc[i][7]);
            if ((cg & 3) == 0) {
                g_als[row * 4 + head] = ps;
                g_ald[row * 4 + head] = pd;
            }
        }
    }
}

// ------ single-pass softmax + aggregation, zero-padded unrolled-8 (layers 0/1) -
__global__ void __launch_bounds__(256)
k_agg(const float* __restrict__ bias) {
    int warp = (blockIdx.x * blockDim.x + threadIdx.x) >> 5;
    int lane = threadIdx.x & 31;
    if (warp >= NN) return;
    int node = warp;
    int start = g_row[node], end = g_row[node + 1];

    int head = lane >> 3;
    int sub = lane & 7;
    float aldh = g_ald[node * 4 + head];
    int c4 = lane * 4;
    float4 acc = make_float4(0.f, 0.f, 0.f, 0.f);
    float den = 0.f;

    for (int base = start; base < end; base += 32) {
        int j = base + lane;
        int sj = (j < end) ? g_srcv[j] : 0;
        // lane (head,sub): exp-weight for edge base+sub+8k under `head`; 0 if OOR
        float er[4];
#pragma unroll
        for (int k = 0; k < 4; k++) {
            int s2 = __shfl_sync(0xffffffffu, sj, sub + 8 * k);
            float e = __ldg(&g_als[s2 * 4 + head]) + aldh;
            e = (e >= 0.f) ? e : 0.2f * e;
            er[k] = (base + sub + 8 * k < end) ? __expf(e) : 0.f;
        }
#pragma unroll
        for (int k8 = 0; k8 < 4; k8++) {
            if (base + 8 * k8 >= end) break;
            float ek = er[k8];
            int s[8];
            float w[8];
#pragma unroll
            for (int u = 0; u < 8; u++) {
                s[u] = __shfl_sync(0xffffffffu, sj, 8 * k8 + u);
                w[u] = __shfl_sync(0xffffffffu, ek, (head << 3) | u);
            }
            float4 hv[8];
#pragma unroll
            for (int u = 0; u < 8; u++)
                hv[u] = *(const float4*)&g_h[(size_t)s[u] * 128 + c4];
#pragma unroll
            for (int u = 0; u < 8; u++) {
                den += w[u];
                acc.x = fmaf(w[u], hv[u].x, acc.x);
                acc.y = fmaf(w[u], hv[u].y, acc.y);
                acc.z = fmaf(w[u], hv[u].z, acc.z);
                acc.w = fmaf(w[u], hv[u].w, acc.w);
            }
        }
    }

    float invd = 1.f / den;
    float4 bv = *(const float4*)&bias[c4];
    float r0 = fmaf(acc.x, invd, bv.x);
    float r1 = fmaf(acc.y, invd, bv.y);
    float r2 = fmaf(acc.z, invd, bv.z);
    float r3 = fmaf(acc.w, invd, bv.w);
    r0 = (r0 > 0.f) ? r0 : expm1f(r0);
    r1 = (r1 > 0.f) ? r1 : expm1f(r1);
    r2 = (r2 > 0.f) ? r2 : expm1f(r2);
    r3 = (r3 > 0.f) ? r3 : expm1f(r3);
    *(float4*)&g_feat[(size_t)node * 128 + c4] = make_float4(r0, r1, r2, r3);
}

// ---------------- layer 2: GEMM (Nout=40) + fused attention dots ---------------
__global__ void __launch_bounds__(256)
k_gemm40(const float* __restrict__ W2,
         const float* __restrict__ a_src2, const float* __restrict__ a_dst2) {
    __shared__ float Wt[128 * 44];
    __shared__ float Xs[32 * 128];
    int t = threadIdx.x;
    int row0 = blockIdx.x * 32;

    for (int idx = t; idx < 40 * 128; idx += 256) {
        int c = idx >> 7, k = idx & 127;
        Wt[k * 44 + c] = W2[idx];
    }
    for (int idx = t; idx < 32 * 32; idx += 256) {
        int r = idx >> 5, c4 = idx & 31;
        int row = row0 + r;
        float4 v = make_float4(0.f, 0.f, 0.f, 0.f);
        if (row < NN) v = *(const float4*)&g_feat[(size_t)row * 128 + c4 * 4];
        *(float4*)&Xs[r * 128 + c4 * 4] = v;
    }

    int cg = t & 7;
    int rg = t >> 3;
    float as[5], ad[5];
#pragma unroll
    for (int j = 0; j < 5; j++) {
        as[j] = __ldg(&a_src2[cg * 5 + j]);
        ad[j] = __ldg(&a_dst2[cg * 5 + j]);
    }
    __syncthreads();

    float acc[5] = {0.f, 0.f, 0.f, 0.f, 0.f};
#pragma unroll 4
    for (int k = 0; k < 128; k++) {
        float a = Xs[rg * 128 + k];
#pragma unroll
        for (int j = 0; j < 5; j++)
            acc[j] = fmaf(a, Wt[k * 44 + cg * 5 + j], acc[j]);
    }

    float ps = 0.f, pd = 0.f;
#pragma unroll
    for (int j = 0; j < 5; j++) {
        ps = fmaf(acc[j], as[j], ps);
        pd = fmaf(acc[j], ad[j], pd);
    }
    ps += __shfl_xor_sync(0xffffffffu, ps, 1);
    ps += __shfl_xor_sync(0xffffffffu, ps, 2);
    ps += __shfl_xor_sync(0xffffffffu, ps, 4);
    pd += __shfl_xor_sync(0xffffffffu, pd, 1);
    pd += __shfl_xor_sync(0xffffffffu, pd, 2);
    pd += __shfl_xor_sync(0xffffffffu, pd, 4);

    int row = row0 + rg;
    if (row < NN) {
#pragma unroll
        for (int j = 0; j < 5; j++)
            g_h[(size_t)row * 40 + cg * 5 + j] = acc[j];
        if (cg == 0) {
            g_als[row] = ps;
            g_ald[row] = pd;
        }
    }
}

// ---- layer 2: single-pass agg (zero-padded unrolled-8) + log_softmax fused ----
__global__ void __launch_bounds__(256)
k_agg2(const float* __restrict__ b2, float* __restrict__ out) {
    int warp = (blockIdx.x * blockDim.x + threadIdx.x) >> 5;
    int lane = threadIdx.x & 31;
    if (warp >= NN) return;
    int node = warp;
    int start = g_row[node], end = g_row[node + 1];
    float aldn = g_ald[node];

    float acc0 = 0.f, acc1 = 0.f, den = 0.f;
    for (int base = start; base < end; base += 32) {
        int j = base + lane;
        int sj = (j < end) ? g_srcv[j] : 0;
        float e = __ldg(&g_als[sj]) + aldn;
        e = (e >= 0.f) ? e : 0.2f * e;
        float al = (j < end) ? __expf(e) : 0.f;   // zero-pad OOR edges
#pragma unroll
        for (int k8 = 0; k8 < 4; k8++) {
            if (base + 8 * k8 >= end) break;
            int s[8];
            float w[8];
#pragma unroll
            for (int u = 0; u < 8; u++) {
                s[u] = __shfl_sync(0xffffffffu, sj, 8 * k8 + u);
                w[u] = __shfl_sync(0xffffffffu, al, 8 * k8 + u);
            }
            float h0[8], h1[8];
#pragma unroll
            for (int u = 0; u < 8; u++) {
                const float* hr = &g_h[(size_t)s[u] * 40];
                h0[u] = hr[lane];
                h1[u] = (lane < 8) ? hr[32 + lane] : 0.f;
            }
#pragma unroll
            for (int u = 0; u < 8; u++) {
                den += w[u];
                acc0 = fmaf(w[u], h0[u], acc0);
                acc1 = fmaf(w[u], h1[u], acc1);
            }
        }
    }
    float invd = 1.f / den;

    float v0 = fmaf(acc0, invd, __ldg(&b2[lane]));
    float v1 = (lane < 8) ? fmaf(acc1, invd, __ldg(&b2[32 + lane])) : -1e30f;
    float mx = fmaxf(v0, v1);
#pragma unroll
    for (int off = 16; off > 0; off >>= 1)
        mx = fmaxf(mx, __shfl_xor_sync(0xffffffffu, mx, off));
    float se = __expf(v0 - mx) + ((lane < 8) ? __expf(v1 - mx) : 0.f);
#pragma unroll
    for (int off = 16; off > 0; off >>= 1)
        se += __shfl_xor_sync(0xffffffffu, se, off);
    float lse = mx + __logf(se);

    out[(size_t)node * 40 + lane] = v0 - lse;
    if (lane < 8) out[(size_t)node * 40 + 32 + lane] = v1 - lse;
}

// ---------------- launch -------------------------------------------------------
extern "C" void kernel_launch(void* const* d_in, const int* in_sizes, int n_in,
                              void* d_out, int out_size) {
    const float* x   = (const float*)d_in[0];
    const void*  ei  = d_in[1];
    const float* W0  = (const float*)d_in[2];
    const float* as0 = (const float*)d_in[3];
    const float* ad0 = (const float*)d_in[4];
    const float* b0  = (const float*)d_in[5];
    const float* W1  = (const float*)d_in[6];
    const float* as1 = (const float*)d_in[7];
    const float* ad1 = (const float*)d_in[8];
    const float* b1  = (const float*)d_in[9];
    const float* W2  = (const float*)d_in[10];
    const float* as2 = (const float*)d_in[11];
    const float* ad2 = (const float*)d_in[12];
    const float* b2  = (const float*)d_in[13];
    float* out = (float*)d_out;

    const int SMEM128 = (128 * 132 + 64 * 128) * (int)sizeof(float);  // 100352
    cudaFuncSetAttribute(k_gemm128, cudaFuncAttributeMaxDynamicSharedMemorySize, SMEM128);

    // CSR build
    k_detect<<<1, 256>>>((const int*)ei);
    k_zero<<<(NN + 511) / 512, 512>>>();
    k_count<<<(ETOT + 511) / 512, 512>>>(ei);
    k_scan1<<<NB, SCAN_B>>>();
    k_scan2<<<1, 128>>>();
    k_scan3<<<(NN + 511) / 512, 512>>>();
    k_fill<<<(ETOT + 511) / 512, 512>>>(ei);

    const int GEMM_BLKS = (NN + 63) / 64;         // 782
    const int AGG_BLKS  = (NN * 32 + 255) / 256;  // one warp per node

    // layer 0
    k_gemm128<<<GEMM_BLKS, 256, SMEM128>>>(x, 0, W0, as0, ad0);
    k_agg<<<AGG_BLKS, 256>>>(b0);

    // layer 1
    k_gemm128<<<GEMM_BLKS, 256, SMEM128>>>(nullptr, 1, W1, as1, ad1);
    k_agg<<<AGG_BLKS, 256>>>(b1);

    // layer 2
    k_gemm40<<<(NN + 31) / 32, 256>>>(W2, as2, ad2);
    k_agg2<<<AGG_BLKS, 256>>>(b2, out);
}

// round 7
// speedup vs baseline: 1.8611x; 1.3070x over previous
#include <cuda_runtime.h>
#include <cuda_bf16.h>
#include <math.h>
#include <cstdint>

#define NN   50000
#define EE0  800000
#define ETOT 850000
#define NH   4
#define SCAN_B 512
#define NB   ((NN + SCAN_B - 1) / SCAN_B)   // 98

// ---------------- scratch (device globals; no allocation allowed) -------------
__device__ __align__(16) float g_feat[(size_t)NN * 128];
__device__ __align__(16) float g_h[(size_t)NN * 128];
__device__ __align__(16) float g_als[NN * NH];
__device__ __align__(16) float g_ald[NN * NH];
__device__ __align__(16) uint32_t g_Wpk[2][16384];   // packed: lo16=bf16 hi, hi16=bf16 lo
__device__ int g_deg[NN];
__device__ int g_row[NN + 1];
__device__ int g_cur[NN];
__device__ int g_bsum[NB];
__device__ int g_boff[NB];
__device__ int g_srcv[ETOT];
__device__ int g_is64;

// ---------------- small helpers -----------------------------------------------
__device__ __forceinline__ uint32_t prmt(uint32_t a, uint32_t b, uint32_t sel) {
    uint32_t d;
    asm("prmt.b32 %0, %1, %2, %3;" : "=r"(d) : "r"(a), "r"(b), "r"(sel));
    return d;
}
__device__ __forceinline__ uint32_t pack_hilo(float x) {
    __nv_bfloat16 h = __float2bfloat16(x);
    float hf = __bfloat162float(h);
    __nv_bfloat16 l = __float2bfloat16(x - hf);
    return (uint32_t)__bfloat16_as_ushort(h) | ((uint32_t)__bfloat16_as_ushort(l) << 16);
}
#define MMA_BF16(d, a, b) \
    asm volatile("mma.sync.aligned.m16n8k16.row.col.f32.bf16.bf16.f32 " \
        "{%0,%1,%2,%3}, {%4,%5,%6,%7}, {%8,%9}, {%0,%1,%2,%3};" \
        : "+f"((d)[0]), "+f"((d)[1]), "+f"((d)[2]), "+f"((d)[3]) \
        : "r"((a)[0]), "r"((a)[1]), "r"((a)[2]), "r"((a)[3]), "r"((b)[0]), "r"((b)[1]))

// ---------------- edge_index dtype detection ---------------------------------
__global__ void k_detect(const int* __restrict__ ei32) {
    __shared__ int zc;
    if (threadIdx.x == 0) zc = 0;
    __syncthreads();
    int z = 0;
    for (int k = threadIdx.x; k < 1024; k += blockDim.x)
        if (ei32[2 * k + 1] == 0) z++;
    atomicAdd(&zc, z);
    __syncthreads();
    if (threadIdx.x == 0) g_is64 = (zc > 512) ? 1 : 0;
}

__device__ __forceinline__ void get_edge(const void* ei, int e, int& s, int& d) {
    if (e >= EE0) { s = e - EE0; d = s; return; }
    if (g_is64) {
        const long long* p = (const long long*)ei;
        s = (int)p[e];
        d = (int)p[EE0 + e];
    } else {
        const int* p = (const int*)ei;
        s = p[e];
        d = p[EE0 + e];
    }
}

__device__ __forceinline__ int get_dst(const void* ei, int e) {
    if (e >= EE0) return e - EE0;
    if (g_is64) return (int)((const long long*)ei)[EE0 + e];
    return ((const int*)ei)[EE0 + e];
}

// ---------------- W split to packed bf16 hi/lo --------------------------------
__global__ void k_convW(const float* __restrict__ W0, const float* __restrict__ W1) {
    int i = blockIdx.x * blockDim.x + threadIdx.x;
    if (i < 16384)       g_Wpk[0][i] = pack_hilo(W0[i]);
    else if (i < 32768)  g_Wpk[1][i - 16384] = pack_hilo(W1[i - 16384]);
}

// ---------------- CSR build ---------------------------------------------------
__global__ void k_zero() {
    int i = blockIdx.x * blockDim.x + threadIdx.x;
    if (i < NN) g_deg[i] = 0;
}

__global__ void k_count(const void* __restrict__ ei) {
    int e = blockIdx.x * blockDim.x + threadIdx.x;
    if (e >= ETOT) return;
    atomicAdd(&g_deg[get_dst(ei, e)], 1);
}

__global__ void k_scan1() {
    __shared__ int sm[SCAN_B];
    int t = threadIdx.x;
    int idx = blockIdx.x * SCAN_B + t;
    int v = (idx < NN) ? g_deg[idx] : 0;
    sm[t] = v;
    __syncthreads();
#pragma unroll
    for (int off = 1; off < SCAN_B; off <<= 1) {
        int p = (t >= off) ? sm[t - off] : 0;
        __syncthreads();
        sm[t] += p;
        __syncthreads();
    }
    if (idx < NN) g_row[idx] = sm[t] - v;
    if (t == SCAN_B - 1) g_bsum[blockIdx.x] = sm[t];
}

__global__ void k_scan2() {
    __shared__ int sm[128];
    int t = threadIdx.x;
    int v = (t < NB) ? g_bsum[t] : 0;
    sm[t] = v;
    __syncthreads();
#pragma unroll
    for (int off = 1; off < 128; off <<= 1) {
        int p = (t >= off) ? sm[t - off] : 0;
        __syncthreads();
        sm[t] += p;
        __syncthreads();
    }
    if (t < NB) g_boff[t] = sm[t] - v;
}

__global__ void k_scan3() {
    int idx = blockIdx.x * blockDim.x + threadIdx.x;
    if (idx < NN) {
        int r = g_row[idx] + g_boff[idx >> 9];
        g_row[idx] = r;
        g_cur[idx] = r;
    }
    if (idx == 0) g_row[NN] = ETOT;
}

__global__ void k_fill(const void* __restrict__ ei) {
    int e = blockIdx.x * blockDim.x + threadIdx.x;
    if (e >= ETOT) return;
    int s, d;
    get_edge(ei, e, s, d);
    int pos = atomicAdd(&g_cur[d], 1);
    g_srcv[pos] = s;
}

// ======= bf16x3 GEMM via mma.sync: h = X @ W^T, 128x128 tile, fused att =======
// smem (dynamic): AS[128]f at 0, AD[128]f at 512, Xp[128][132]u32 at 1024,
// Wp[128][132]u32 at 68608. total 136192 B.
#define SM_AS 0
#define SM_AD 512
#define SM_XP 1024
#define SM_WP 68608
#define SM_TOT 136192

__global__ void __launch_bounds__(512, 1)
k_gemm_mma(const float* __restrict__ xin, int use_gfeat, int widx,
           const float* __restrict__ a_src, const float* __restrict__ a_dst) {
    extern __shared__ char smem[];
    float* AS = (float*)(smem + SM_AS);
    float* AD = (float*)(smem + SM_AD);
    uint32_t* Xp = (uint32_t*)(smem + SM_XP);   // [128][132]
    uint32_t* Wp = (uint32_t*)(smem + SM_WP);   // [128][132]
    const float* in = use_gfeat ? g_feat : xin;
    int tid = threadIdx.x;
    int row0 = blockIdx.x * 128;

    if (tid < 128) {
        AS[tid] = a_src[tid];
        AD[tid] = a_dst[tid];
    }
    // stage X (fp32 -> packed bf16 hi|lo)
    for (int idx = tid; idx < 128 * 32; idx += 512) {
        int r = idx >> 5, c4 = (idx & 31) * 4;
        int row = row0 + r;
        float4 v = make_float4(0.f, 0.f, 0.f, 0.f);
        if (row < NN) v = *(const float4*)&in[(size_t)row * 128 + c4];
        uint32_t* dst = &Xp[r * 132 + c4];
        dst[0] = pack_hilo(v.x);
        dst[1] = pack_hilo(v.y);
        dst[2] = pack_hilo(v.z);
        dst[3] = pack_hilo(v.w);
    }
    // stage W (already packed)
    {
        const uint32_t* wsrc = g_Wpk[widx];
        for (int idx = tid; idx < 16384; idx += 512) {
            int n = idx >> 7, k = idx & 127;
            Wp[n * 132 + k] = wsrc[idx];
        }
    }
    __syncthreads();

    int w = tid >> 5;
    int lane = tid & 31;
    int g = lane >> 2;        // 0..7
    int tig = lane & 3;       // 0..3
    int rw = (w & 7) * 16;    // warp row base
    int cw = (w >> 3) * 64;   // warp col base (0 or 64)

    float acc[8][4];
#pragma unroll
    for (int i = 0; i < 8; i++)
#pragma unroll
        for (int j = 0; j < 4; j++) acc[i][j] = 0.f;

#pragma unroll
    for (int kt = 0; kt < 8; kt++) {
        int kk = kt * 16 + 2 * tig;
        int rA = rw + g, rB = rA + 8;
        uint2 w0 = *(const uint2*)&Xp[rA * 132 + kk];
        uint2 w1 = *(const uint2*)&Xp[rB * 132 + kk];
        uint2 w2 = *(const uint2*)&Xp[rA * 132 + kk + 8];
        uint2 w3 = *(const uint2*)&Xp[rB * 132 + kk + 8];
        uint32_t ahi[4], alo[4];
        ahi[0] = prmt(w0.x, w0.y, 0x5410); alo[0] = prmt(w0.x, w0.y, 0x7632);
        ahi[1] = prmt(w1.x, w1.y, 0x5410); alo[1] = prmt(w1.x, w1.y, 0x7632);
        ahi[2] = prmt(w2.x, w2.y, 0x5410); alo[2] = prmt(w2.x, w2.y, 0x7632);
        ahi[3] = prmt(w3.x, w3.y, 0x5410); alo[3] = prmt(w3.x, w3.y, 0x7632);
#pragma unroll
        for (int nt = 0; nt < 8; nt++) {
            int nc = cw + nt * 8 + g;
            uint2 b0 = *(const uint2*)&Wp[nc * 132 + kk];
            uint2 b1 = *(const uint2*)&Wp[nc * 132 + kk + 8];
            uint32_t bhi[2], blo[2];
            bhi[0] = prmt(b0.x, b0.y, 0x5410); blo[0] = prmt(b0.x, b0.y, 0x7632);
            bhi[1] = prmt(b1.x, b1.y, 0x5410); blo[1] = prmt(b1.x, b1.y, 0x7632);
            MMA_BF16(acc[nt], ahi, bhi);
            MMA_BF16(acc[nt], ahi, blo);
            MMA_BF16(acc[nt], alo, bhi);
        }
    }

    // epilogue: rows rw+g and rw+g+8; cols cw + nt*8 + 2tig (+1)
    int rowA = row0 + rw + g;
    int rowB = rowA + 8;
    int h0 = (w >> 3) * 2;       // first head of this col-half
    float ps0[2] = {0.f, 0.f}, ps1[2] = {0.f, 0.f};
    float pd0[2] = {0.f, 0.f}, pd1[2] = {0.f, 0.f};
#pragma unroll
    for (int nt = 0; nt < 8; nt++) {
        int h = nt >> 2;
        int c = cw + nt * 8 + 2 * tig;
        float a0 = AS[c], a1 = AS[c + 1];
        float d0 = AD[c], d1 = AD[c + 1];
        ps0[h] += acc[nt][0] * a0 + acc[nt][1] * a1;
        ps1[h] += acc[nt][2] * a0 + acc[nt][3] * a1;
        pd0[h] += acc[nt][0] * d0 + acc[nt][1] * d1;
        pd1[h] += acc[nt][2] * d0 + acc[nt][3] * d1;
        if (rowA < NN)
            *(float2*)&g_h[(size_t)rowA * 128 + c] = make_float2(acc[nt][0], acc[nt][1]);
        if (rowB < NN)
            *(float2*)&g_h[(size_t)rowB * 128 + c] = make_float2(acc[nt][2], acc[nt][3]);
    }
#pragma unroll
    for (int h = 0; h < 2; h++) {
        ps0[h] += __shfl_xor_sync(0xffffffffu, ps0[h], 1);
        ps0[h] += __shfl_xor_sync(0xffffffffu, ps0[h], 2);
        ps1[h] += __shfl_xor_sync(0xffffffffu, ps1[h], 1);
        ps1[h] += __shfl_xor_sync(0xffffffffu, ps1[h], 2);
        pd0[h] += __shfl_xor_sync(0xffffffffu, pd0[h], 1);
        pd0[h] += __shfl_xor_sync(0xffffffffu, pd0[h], 2);
        pd1[h] += __shfl_xor_sync(0xffffffffu, pd1[h], 1);
        pd1[h] += __shfl_xor_sync(0xffffffffu, pd1[h], 2);
    }
    if (tig == 0) {
#pragma unroll
        for (int h = 0; h < 2; h++) {
            if (rowA < NN) {
                g_als[rowA * 4 + h0 + h] = ps0[h];
                g_ald[rowA * 4 + h0 + h] = pd0[h];
            }
            if (rowB < NN) {
                g_als[rowB * 4 + h0 + h] = ps1[h];
                g_ald[rowB * 4 + h0 + h] = pd1[h];
            }
        }
    }
}

// ------ single-pass softmax + aggregation, zero-padded unrolled-8 (layers 0/1) -
__global__ void __launch_bounds__(256)
k_agg(const float* __restrict__ bias) {
    int warp = (blockIdx.x * blockDim.x + threadIdx.x) >> 5;
    int lane = threadIdx.x & 31;
    if (warp >= NN) return;
    int node = warp;
    int start = g_row[node], end = g_row[node + 1];

    int head = lane >> 3;
    int sub = lane & 7;
    float aldh = g_ald[node * 4 + head];
    int c4 = lane * 4;
    float4 acc = make_float4(0.f, 0.f, 0.f, 0.f);
    float den = 0.f;

    for (int base = start; base < end; base += 32) {
        int j = base + lane;
        int sj = (j < end) ? g_srcv[j] : 0;
        float er[4];
#pragma unroll
        for (int k = 0; k < 4; k++) {
            int s2 = __shfl_sync(0xffffffffu, sj, sub + 8 * k);
            float e = __ldg(&g_als[s2 * 4 + head]) + aldh;
            e = (e >= 0.f) ? e : 0.2f * e;
            er[k] = (base + sub + 8 * k < end) ? __expf(e) : 0.f;
        }
#pragma unroll
        for (int k8 = 0; k8 < 4; k8++) {
            if (base + 8 * k8 >= end) break;
            float ek = er[k8];
            int s[8];
            float w[8];
#pragma unroll
            for (int u = 0; u < 8; u++) {
                s[u] = __shfl_sync(0xffffffffu, sj, 8 * k8 + u);
                w[u] = __shfl_sync(0xffffffffu, ek, (head << 3) | u);
            }
            float4 hv[8];
#pragma unroll
            for (int u = 0; u < 8; u++)
                hv[u] = *(const float4*)&g_h[(size_t)s[u] * 128 + c4];
#pragma unroll
            for (int u = 0; u < 8; u++) {
                den += w[u];
                acc.x = fmaf(w[u], hv[u].x, acc.x);
                acc.y = fmaf(w[u], hv[u].y, acc.y);
                acc.z = fmaf(w[u], hv[u].z, acc.z);
                acc.w = fmaf(w[u], hv[u].w, acc.w);
            }
        }
    }

    float invd = 1.f / den;
    float4 bv = *(const float4*)&bias[c4];
    float r0 = fmaf(acc.x, invd, bv.x);
    float r1 = fmaf(acc.y, invd, bv.y);
    float r2 = fmaf(acc.z, invd, bv.z);
    float r3 = fmaf(acc.w, invd, bv.w);
    r0 = (r0 > 0.f) ? r0 : expm1f(r0);
    r1 = (r1 > 0.f) ? r1 : expm1f(r1);
    r2 = (r2 > 0.f) ? r2 : expm1f(r2);
    r3 = (r3 > 0.f) ? r3 : expm1f(r3);
    *(float4*)&g_feat[(size_t)node * 128 + c4] = make_float4(r0, r1, r2, r3);
}

// ---------------- layer 2: GEMM (Nout=40) + fused attention dots ---------------
__global__ void __launch_bounds__(256)
k_gemm40(const float* __restrict__ W2,
         const float* __restrict__ a_src2, const float* __restrict__ a_dst2) {
    __shared__ float Wt[128 * 44];
    __shared__ float Xs[32 * 128];
    int t = threadIdx.x;
    int row0 = blockIdx.x * 32;

    for (int idx = t; idx < 40 * 128; idx += 256) {
        int c = idx >> 7, k = idx & 127;
        Wt[k * 44 + c] = W2[idx];
    }
    for (int idx = t; idx < 32 * 32; idx += 256) {
        int r = idx >> 5, c4 = idx & 31;
        int row = row0 + r;
        float4 v = make_float4(0.f, 0.f, 0.f, 0.f);
        if (row < NN) v = *(const float4*)&g_feat[(size_t)row * 128 + c4 * 4];
        *(float4*)&Xs[r * 128 + c4 * 4] = v;
    }

    int cg = t & 7;
    int rg = t >> 3;
    float as[5], ad[5];
#pragma unroll
    for (int j = 0; j < 5; j++) {
        as[j] = __ldg(&a_src2[cg * 5 + j]);
        ad[j] = __ldg(&a_dst2[cg * 5 + j]);
    }
    __syncthreads();

    float acc[5] = {0.f, 0.f, 0.f, 0.f, 0.f};
#pragma unroll 4
    for (int k = 0; k < 128; k++) {
        float a = Xs[rg * 128 + k];
#pragma unroll
        for (int j = 0; j < 5; j++)
            acc[j] = fmaf(a, Wt[k * 44 + cg * 5 + j], acc[j]);
    }

    float ps = 0.f, pd = 0.f;
#pragma unroll
    for (int j = 0; j < 5; j++) {
        ps = fmaf(acc[j], as[j], ps);
        pd = fmaf(acc[j], ad[j], pd);
    }
    ps += __shfl_xor_sync(0xffffffffu, ps, 1);
    ps += __shfl_xor_sync(0xffffffffu, ps, 2);
    ps += __shfl_xor_sync(0xffffffffu, ps, 4);
    pd += __shfl_xor_sync(0xffffffffu, pd, 1);
    pd += __shfl_xor_sync(0xffffffffu, pd, 2);
    pd += __shfl_xor_sync(0xffffffffu, pd, 4);

    int row = row0 + rg;
    if (row < NN) {
#pragma unroll
        for (int j = 0; j < 5; j++)
            g_h[(size_t)row * 40 + cg * 5 + j] = acc[j];
        if (cg == 0) {
            g_als[row] = ps;
            g_ald[row] = pd;
        }
    }
}

// ---- layer 2: single-pass agg (zero-padded unrolled-8) + log_softmax fused ----
__global__ void __launch_bounds__(256)
k_agg2(const float* __restrict__ b2, float* __restrict__ out) {
    int warp = (blockIdx.x * blockDim.x + threadIdx.x) >> 5;
    int lane = threadIdx.x & 31;
    if (warp >= NN) return;
    int node = warp;
    int start = g_row[node], end = g_row[node + 1];
    float aldn = g_ald[node];

    float acc0 = 0.f, acc1 = 0.f, den = 0.f;
    for (int base = start; base < end; base += 32) {
        int j = base + lane;
        int sj = (j < end) ? g_srcv[j] : 0;
        float e = __ldg(&g_als[sj]) + aldn;
        e = (e >= 0.f) ? e : 0.2f * e;
        float al = (j < end) ? __expf(e) : 0.f;
#pragma unroll
        for (int k8 = 0; k8 < 4; k8++) {
            if (base + 8 * k8 >= end) break;
            int s[8];
            float w[8];
#pragma unroll
            for (int u = 0; u < 8; u++) {
                s[u] = __shfl_sync(0xffffffffu, sj, 8 * k8 + u);
                w[u] = __shfl_sync(0xffffffffu, al, 8 * k8 + u);
            }
            float h0[8], h1[8];
#pragma unroll
            for (int u = 0; u < 8; u++) {
                const float* hr = &g_h[(size_t)s[u] * 40];
                h0[u] = hr[lane];
                h1[u] = (lane < 8) ? hr[32 + lane] : 0.f;
            }
#pragma unroll
            for (int u = 0; u < 8; u++) {
                den += w[u];
                acc0 = fmaf(w[u], h0[u], acc0);
                acc1 = fmaf(w[u], h1[u], acc1);
            }
        }
    }
    float invd = 1.f / den;

    float v0 = fmaf(acc0, invd, __ldg(&b2[lane]));
    float v1 = (lane < 8) ? fmaf(acc1, invd, __ldg(&b2[32 + lane])) : -1e30f;
    float mx = fmaxf(v0, v1);
#pragma unroll
    for (int off = 16; off > 0; off >>= 1)
        mx = fmaxf(mx, __shfl_xor_sync(0xffffffffu, mx, off));
    float se = __expf(v0 - mx) + ((lane < 8) ? __expf(v1 - mx) : 0.f);
#pragma unroll
    for (int off = 16; off > 0; off >>= 1)
        se += __shfl_xor_sync(0xffffffffu, se, off);
    float lse = mx + __logf(se);

    out[(size_t)node * 40 + lane] = v0 - lse;
    if (lane < 8) out[(size_t)node * 40 + 32 + lane] = v1 - lse;
}

// ---------------- launch -------------------------------------------------------
extern "C" void kernel_launch(void* const* d_in, const int* in_sizes, int n_in,
                              void* d_out, int out_size) {
    const float* x   = (const float*)d_in[0];
    const void*  ei  = d_in[1];
    const float* W0  = (const float*)d_in[2];
    const float* as0 = (const float*)d_in[3];
    const float* ad0 = (const float*)d_in[4];
    const float* b0  = (const float*)d_in[5];
    const float* W1  = (const float*)d_in[6];
    const float* as1 = (const float*)d_in[7];
    const float* ad1 = (const float*)d_in[8];
    const float* b1  = (const float*)d_in[9];
    const float* W2  = (const float*)d_in[10];
    const float* as2 = (const float*)d_in[11];
    const float* ad2 = (const float*)d_in[12];
    const float* b2  = (const float*)d_in[13];
    float* out = (float*)d_out;

    cudaFuncSetAttribute(k_gemm_mma, cudaFuncAttributeMaxDynamicSharedMemorySize, SM_TOT);

    // W packed bf16 hi/lo split + CSR build
    k_convW<<<(32768 + 255) / 256, 256>>>(W0, W1);
    k_detect<<<1, 256>>>((const int*)ei);
    k_zero<<<(NN + 511) / 512, 512>>>();
    k_count<<<(ETOT + 511) / 512, 512>>>(ei);
    k_scan1<<<NB, SCAN_B>>>();
    k_scan2<<<1, 128>>>();
    k_scan3<<<(NN + 511) / 512, 512>>>();
    k_fill<<<(ETOT + 511) / 512, 512>>>(ei);

    const int TC_BLKS  = (NN + 127) / 128;        // 391
    const int AGG_BLKS = (NN * 32 + 255) / 256;   // one warp per node

    // layer 0
    k_gemm_mma<<<TC_BLKS, 512, SM_TOT>>>(x, 0, 0, as0, ad0);
    k_agg<<<AGG_BLKS, 256>>>(b0);

    // layer 1
    k_gemm_mma<<<TC_BLKS, 512, SM_TOT>>>(nullptr, 1, 1, as1, ad1);
    k_agg<<<AGG_BLKS, 256>>>(b1);

    // layer 2
    k_gemm40<<<(NN + 31) / 32, 256>>>(W2, as2, ad2);
    k_agg2<<<AGG_BLKS, 256>>>(b2, out);
}

// round 8
// speedup vs baseline: 2.0953x; 1.1258x over previous
#include <cuda_runtime.h>
#include <cuda_bf16.h>
#include <cuda_fp16.h>
#include <math.h>
#include <cstdint>

#define NN   50000
#define EE0  800000
#define ETOT 850000
#define NH   4
#define SCAN_B 512
#define NB   ((NN + SCAN_B - 1) / SCAN_B)   // 98

// ---------------- scratch (device globals; no allocation allowed) -------------
__device__ __align__(16) float g_feat[(size_t)NN * 128];
__device__ __align__(16) __half g_h01[(size_t)NN * 128];   // layers 0/1 h (fp16)
__device__ __align__(16) float g_h2[(size_t)NN * 40];      // layer 2 h (fp32)
__device__ __align__(16) float g_als[NN * NH];
__device__ __align__(16) float g_ald[NN * NH];
__device__ __align__(16) __nv_bfloat16 g_Whi[2][16384];
__device__ __align__(16) __nv_bfloat16 g_Wlo[2][16384];
__device__ int g_deg[NN];
__device__ int g_row[NN + 1];
__device__ int g_cur[NN];
__device__ int g_bsum[NB];
__device__ int g_boff[NB];
__device__ int g_srcv[ETOT];
__device__ int g_is64;

// ---------------- small helpers -----------------------------------------------
#define MMA_BF16(d, a, b) \
    asm volatile("mma.sync.aligned.m16n8k16.row.col.f32.bf16.bf16.f32 " \
        "{%0,%1,%2,%3}, {%4,%5,%6,%7}, {%8,%9}, {%0,%1,%2,%3};" \
        : "+f"((d)[0]), "+f"((d)[1]), "+f"((d)[2]), "+f"((d)[3]) \
        : "r"((a)[0]), "r"((a)[1]), "r"((a)[2]), "r"((a)[3]), "r"((b)[0]), "r"((b)[1]))

__device__ __forceinline__ void split_bf16(float x, __nv_bfloat16& h, __nv_bfloat16& l) {
    h = __float2bfloat16(x);
    l = __float2bfloat16(x - __bfloat162float(h));
}
__device__ __forceinline__ uint32_t bfpair(__nv_bfloat16 a, __nv_bfloat16 b) {
    return (uint32_t)__bfloat16_as_ushort(a) | ((uint32_t)__bfloat16_as_ushort(b) << 16);
}

// ---------------- edge access --------------------------------------------------
__device__ __forceinline__ void get_edge(const void* ei, int e, int& s, int& d) {
    if (e >= EE0) { s = e - EE0; d = s; return; }
    if (g_is64) {
        const long long* p = (const long long*)ei;
        s = (int)p[e];
        d = (int)p[EE0 + e];
    } else {
        const int* p = (const int*)ei;
        s = p[e];
        d = p[EE0 + e];
    }
}
__device__ __forceinline__ int get_dst(const void* ei, int e) {
    if (e >= EE0) return e - EE0;
    if (g_is64) return (int)((const long long*)ei)[EE0 + e];
    return ((const int*)ei)[EE0 + e];
}

// ------------- prep: dtype detect + deg zero + W hi/lo split (fused) -----------
__global__ void k_prep(const int* __restrict__ ei32,
                       const float* __restrict__ W0, const float* __restrict__ W1) {
    int i = blockIdx.x * blockDim.x + threadIdx.x;
    if (blockIdx.x == 0) {
        __shared__ int zc;
        if (threadIdx.x == 0) zc = 0;
        __syncthreads();
        int z = 0;
        for (int k = threadIdx.x; k < 1024; k += blockDim.x)
            if (ei32[2 * k + 1] == 0) z++;
        atomicAdd(&zc, z);
        __syncthreads();
        if (threadIdx.x == 0) g_is64 = (zc > 512) ? 1 : 0;
    }
    if (i < NN) g_deg[i] = 0;
    if (i < 16384) {
        split_bf16(W0[i], g_Whi[0][i], g_Wlo[0][i]);
    } else if (i < 32768) {
        split_bf16(W1[i - 16384], g_Whi[1][i - 16384], g_Wlo[1][i - 16384]);
    }
}

// ---------------- CSR build ---------------------------------------------------
__global__ void k_count(const void* __restrict__ ei) {
    int e = blockIdx.x * blockDim.x + threadIdx.x;
    if (e >= ETOT) return;
    atomicAdd(&g_deg[get_dst(ei, e)], 1);
}

__global__ void k_scan1() {
    __shared__ int sm[SCAN_B];
    int t = threadIdx.x;
    int idx = blockIdx.x * SCAN_B + t;
    int v = (idx < NN) ? g_deg[idx] : 0;
    sm[t] = v;
    __syncthreads();
#pragma unroll
    for (int off = 1; off < SCAN_B; off <<= 1) {
        int p = (t >= off) ? sm[t - off] : 0;
        __syncthreads();
        sm[t] += p;
        __syncthreads();
    }
    if (idx < NN) g_row[idx] = sm[t] - v;
    if (t == SCAN_B - 1) g_bsum[blockIdx.x] = sm[t];
}

__global__ void k_scan2() {
    __shared__ int sm[128];
    int t = threadIdx.x;
    int v = (t < NB) ? g_bsum[t] : 0;
    sm[t] = v;
    __syncthreads();
#pragma unroll
    for (int off = 1; off < 128; off <<= 1) {
        int p = (t >= off) ? sm[t - off] : 0;
        __syncthreads();
        sm[t] += p;
        __syncthreads();
    }
    if (t < NB) g_boff[t] = sm[t] - v;
}

__global__ void k_scan3() {
    int idx = blockIdx.x * blockDim.x + threadIdx.x;
    if (idx < NN) {
        int r = g_row[idx] + g_boff[idx >> 9];
        g_row[idx] = r;
        g_cur[idx] = r;
    }
    if (idx == 0) g_row[NN] = ETOT;
}

__global__ void k_fill(const void* __restrict__ ei) {
    int e = blockIdx.x * blockDim.x + threadIdx.x;
    if (e >= ETOT) return;
    int s, d;
    get_edge(ei, e, s, d);
    int pos = atomicAdd(&g_cur[d], 1);
    g_srcv[pos] = s;
}

// ======= bf16x3 GEMM via mma.sync (separate hi/lo smem), fused att dots =======
// smem: AS[128]f @0, AD[128]f @512, then 4 bf16 arrays [128][136]:
#define SMH_XHI 1024
#define SMH_XLO (SMH_XHI + 128 * 136 * 2)
#define SMH_WHI (SMH_XLO + 128 * 136 * 2)
#define SMH_WLO (SMH_WHI + 128 * 136 * 2)
#define SMH_TOT (SMH_WLO + 128 * 136 * 2)   // 140288

__global__ void __launch_bounds__(512, 1)
k_gemm_mma(const float* __restrict__ xin, int use_gfeat, int widx,
           const float* __restrict__ a_src, const float* __restrict__ a_dst) {
    extern __shared__ char smem[];
    float* AS = (float*)(smem);
    float* AD = (float*)(smem + 512);
    __nv_bfloat16* Xhi = (__nv_bfloat16*)(smem + SMH_XHI);
    __nv_bfloat16* Xlo = (__nv_bfloat16*)(smem + SMH_XLO);
    __nv_bfloat16* Whi = (__nv_bfloat16*)(smem + SMH_WHI);
    __nv_bfloat16* Wlo = (__nv_bfloat16*)(smem + SMH_WLO);
    const float* in = use_gfeat ? g_feat : xin;
    int tid = threadIdx.x;
    int row0 = blockIdx.x * 128;

    if (tid < 128) {
        AS[tid] = a_src[tid];
        AD[tid] = a_dst[tid];
    }
    // stage X: fp32 -> bf16 hi/lo in separate arrays
    for (int idx = tid; idx < 128 * 32; idx += 512) {
        int r = idx >> 5, c4 = (idx & 31) * 4;
        int row = row0 + r;
        float4 v = make_float4(0.f, 0.f, 0.f, 0.f);
        if (row < NN) v = *(const float4*)&in[(size_t)row * 128 + c4];
        __nv_bfloat16 h0, h1, h2, h3, l0, l1, l2, l3;
        split_bf16(v.x, h0, l0);
        split_bf16(v.y, h1, l1);
        split_bf16(v.z, h2, l2);
        split_bf16(v.w, h3, l3);
        uint32_t* dh = (uint32_t*)(Xhi + r * 136 + c4);
        uint32_t* dl = (uint32_t*)(Xlo + r * 136 + c4);
        dh[0] = bfpair(h0, h1);
        dh[1] = bfpair(h2, h3);
        dl[0] = bfpair(l0, l1);
        dl[1] = bfpair(l2, l3);
    }
    // stage W hi/lo (pre-split in global): uint4 = 8 bf16 per move
    {
        const __nv_bfloat16* whi = g_Whi[widx];
        const __nv_bfloat16* wlo = g_Wlo[widx];
        for (int idx = tid; idx < 2048; idx += 512) {
            int n = idx >> 4, kc = (idx & 15) * 8;
            *(uint4*)(Whi + n * 136 + kc) = *(const uint4*)(whi + n * 128 + kc);
            *(uint4*)(Wlo + n * 136 + kc) = *(const uint4*)(wlo + n * 128 + kc);
        }
    }
    __syncthreads();

    int w = tid >> 5;
    int lane = tid & 31;
    int g = lane >> 2;        // 0..7
    int tig = lane & 3;       // 0..3
    int rw = (w & 7) * 16;    // warp row base
    int cw = (w >> 3) * 64;   // warp col base (0 or 64)

    float acc[8][4];
#pragma unroll
    for (int i = 0; i < 8; i++)
#pragma unroll
        for (int j = 0; j < 4; j++) acc[i][j] = 0.f;

#pragma unroll
    for (int kt = 0; kt < 8; kt++) {
        int kk = kt * 16 + 2 * tig;
        int rA = rw + g, rB = rA + 8;
        uint32_t ahi[4], alo[4];
        ahi[0] = *(const uint32_t*)(Xhi + rA * 136 + kk);
        ahi[1] = *(const uint32_t*)(Xhi + rB * 136 + kk);
        ahi[2] = *(const uint32_t*)(Xhi + rA * 136 + kk + 8);
        ahi[3] = *(const uint32_t*)(Xhi + rB * 136 + kk + 8);
        alo[0] = *(const uint32_t*)(Xlo + rA * 136 + kk);
        alo[1] = *(const uint32_t*)(Xlo + rB * 136 + kk);
        alo[2] = *(const uint32_t*)(Xlo + rA * 136 + kk + 8);
        alo[3] = *(const uint32_t*)(Xlo + rB * 136 + kk + 8);
#pragma unroll
        for (int nt = 0; nt < 8; nt++) {
            int nc = cw + nt * 8 + g;
            uint32_t bhi[2], blo[2];
            bhi[0] = *(const uint32_t*)(Whi + nc * 136 + kk);
            bhi[1] = *(const uint32_t*)(Whi + nc * 136 + kk + 8);
            blo[0] = *(const uint32_t*)(Wlo + nc * 136 + kk);
            blo[1] = *(const uint32_t*)(Wlo + nc * 136 + kk + 8);
            MMA_BF16(acc[nt], ahi, bhi);
            MMA_BF16(acc[nt], ahi, blo);
            MMA_BF16(acc[nt], alo, bhi);
        }
    }

    // epilogue: rows rw+g, rw+g+8; cols cw + nt*8 + 2tig(+1); h stored fp16
    int rowA = row0 + rw + g;
    int rowB = rowA + 8;
    int h0 = (w >> 3) * 2;
    float ps0[2] = {0.f, 0.f}, ps1[2] = {0.f, 0.f};
    float pd0[2] = {0.f, 0.f}, pd1[2] = {0.f, 0.f};
#pragma unroll
    for (int nt = 0; nt < 8; nt++) {
        int h = nt >> 2;
        int c = cw + nt * 8 + 2 * tig;
        float a0 = AS[c], a1 = AS[c + 1];
        float d0 = AD[c], d1 = AD[c + 1];
        ps0[h] += acc[nt][0] * a0 + acc[nt][1] * a1;
        ps1[h] += acc[nt][2] * a0 + acc[nt][3] * a1;
        pd0[h] += acc[nt][0] * d0 + acc[nt][1] * d1;
        pd1[h] += acc[nt][2] * d0 + acc[nt][3] * d1;
        if (rowA < NN)
            *(__half2*)&g_h01[(size_t)rowA * 128 + c] = __floats2half2_rn(acc[nt][0], acc[nt][1]);
        if (rowB < NN)
            *(__half2*)&g_h01[(size_t)rowB * 128 + c] = __floats2half2_rn(acc[nt][2], acc[nt][3]);
    }
#pragma unroll
    for (int h = 0; h < 2; h++) {
        ps0[h] += __shfl_xor_sync(0xffffffffu, ps0[h], 1);
        ps0[h] += __shfl_xor_sync(0xffffffffu, ps0[h], 2);
        ps1[h] += __shfl_xor_sync(0xffffffffu, ps1[h], 1);
        ps1[h] += __shfl_xor_sync(0xffffffffu, ps1[h], 2);
        pd0[h] += __shfl_xor_sync(0xffffffffu, pd0[h], 1);
        pd0[h] += __shfl_xor_sync(0xffffffffu, pd0[h], 2);
        pd1[h] += __shfl_xor_sync(0xffffffffu, pd1[h], 1);
        pd1[h] += __shfl_xor_sync(0xffffffffu, pd1[h], 2);
    }
    if (tig == 0) {
#pragma unroll
        for (int h = 0; h < 2; h++) {
            if (rowA < NN) {
                g_als[rowA * 4 + h0 + h] = ps0[h];
                g_ald[rowA * 4 + h0 + h] = pd0[h];
            }
            if (rowB < NN) {
                g_als[rowB * 4 + h0 + h] = ps1[h];
                g_ald[rowB * 4 + h0 + h] = pd1[h];
            }
        }
    }
}

// --- single-pass softmax + aggregation, fp16 gather, unrolled-8 (layers 0/1) ---
__global__ void __launch_bounds__(256)
k_agg(const float* __restrict__ bias) {
    int warp = (blockIdx.x * blockDim.x + threadIdx.x) >> 5;
    int lane = threadIdx.x & 31;
    if (warp >= NN) return;
    int node = warp;
    int start = g_row[node], end = g_row[node + 1];

    int head = lane >> 3;
    int sub = lane & 7;
    float aldh = g_ald[node * 4 + head];
    int c4 = lane * 4;
    float4 acc = make_float4(0.f, 0.f, 0.f, 0.f);
    float den = 0.f;

    for (int base = start; base < end; base += 32) {
        int j = base + lane;
        int sj = (j < end) ? g_srcv[j] : 0;
        float er[4];
#pragma unroll
        for (int k = 0; k < 4; k++) {
            int s2 = __shfl_sync(0xffffffffu, sj, sub + 8 * k);
            float e = __ldg(&g_als[s2 * 4 + head]) + aldh;
            e = (e >= 0.f) ? e : 0.2f * e;
            er[k] = (base + sub + 8 * k < end) ? __expf(e) : 0.f;
        }
#pragma unroll
        for (int k8 = 0; k8 < 4; k8++) {
            if (base + 8 * k8 >= end) break;
            float ek = er[k8];
            int s[8];
            float w[8];
#pragma unroll
            for (int u = 0; u < 8; u++) {
                s[u] = __shfl_sync(0xffffffffu, sj, 8 * k8 + u);
                w[u] = __shfl_sync(0xffffffffu, ek, (head << 3) | u);
            }
            uint2 hv[8];
#pragma unroll
            for (int u = 0; u < 8; u++)
                hv[u] = *(const uint2*)(g_h01 + (size_t)s[u] * 128 + c4);
#pragma unroll
            for (int u = 0; u < 8; u++) {
                float2 fa = __half22float2(*reinterpret_cast<__half2*>(&hv[u].x));
                float2 fb = __half22float2(*reinterpret_cast<__half2*>(&hv[u].y));
                den += w[u];
                acc.x = fmaf(w[u], fa.x, acc.x);
                acc.y = fmaf(w[u], fa.y, acc.y);
                acc.z = fmaf(w[u], fb.x, acc.z);
                acc.w = fmaf(w[u], fb.y, acc.w);
            }
        }
    }

    float invd = 1.f / den;
    float4 bv = *(const float4*)&bias[c4];
    float r0 = fmaf(acc.x, invd, bv.x);
    float r1 = fmaf(acc.y, invd, bv.y);
    float r2 = fmaf(acc.z, invd, bv.z);
    float r3 = fmaf(acc.w, invd, bv.w);
    r0 = (r0 > 0.f) ? r0 : expm1f(r0);
    r1 = (r1 > 0.f) ? r1 : expm1f(r1);
    r2 = (r2 > 0.f) ? r2 : expm1f(r2);
    r3 = (r3 > 0.f) ? r3 : expm1f(r3);
    *(float4*)&g_feat[(size_t)node * 128 + c4] = make_float4(r0, r1, r2, r3);
}

// ---------------- layer 2: GEMM (Nout=40) + fused attention dots ---------------
__global__ void __launch_bounds__(256)
k_gemm40(const float* __restrict__ W2,
         const float* __restrict__ a_src2, const float* __restrict__ a_dst2) {
    __shared__ float Wt[128 * 44];
    __shared__ float Xs[32 * 128];
    int t = threadIdx.x;
    int row0 = blockIdx.x * 32;

    for (int idx = t; idx < 40 * 128; idx += 256) {
        int c = idx >> 7, k = idx & 127;
        Wt[k * 44 + c] = W2[idx];
    }
    for (int idx = t; idx < 32 * 32; idx += 256) {
        int r = idx >> 5, c4 = idx & 31;
        int row = row0 + r;
        float4 v = make_float4(0.f, 0.f, 0.f, 0.f);
        if (row < NN) v = *(const float4*)&g_feat[(size_t)row * 128 + c4 * 4];
        *(float4*)&Xs[r * 128 + c4 * 4] = v;
    }

    int cg = t & 7;
    int rg = t >> 3;
    float as[5], ad[5];
#pragma unroll
    for (int j = 0; j < 5; j++) {
        as[j] = __ldg(&a_src2[cg * 5 + j]);
        ad[j] = __ldg(&a_dst2[cg * 5 + j]);
    }
    __syncthreads();

    float acc[5] = {0.f, 0.f, 0.f, 0.f, 0.f};
#pragma unroll 4
    for (int k = 0; k < 128; k++) {
        float a = Xs[rg * 128 + k];
#pragma unroll
        for (int j = 0; j < 5; j++)
            acc[j] = fmaf(a, Wt[k * 44 + cg * 5 + j], acc[j]);
    }

    float ps = 0.f, pd = 0.f;
#pragma unroll
    for (int j = 0; j < 5; j++) {
        ps = fmaf(acc[j], as[j], ps);
        pd = fmaf(acc[j], ad[j], pd);
    }
    ps += __shfl_xor_sync(0xffffffffu, ps, 1);
    ps += __shfl_xor_sync(0xffffffffu, ps, 2);
    ps += __shfl_xor_sync(0xffffffffu, ps, 4);
    pd += __shfl_xor_sync(0xffffffffu, pd, 1);
    pd += __shfl_xor_sync(0xffffffffu, pd, 2);
    pd += __shfl_xor_sync(0xffffffffu, pd, 4);

    int row = row0 + rg;
    if (row < NN) {
#pragma unroll
        for (int j = 0; j < 5; j++)
            g_h2[(size_t)row * 40 + cg * 5 + j] = acc[j];
        if (cg == 0) {
            g_als[row] = ps;
            g_ald[row] = pd;
        }
    }
}

// ---- layer 2: single-pass agg (zero-padded unrolled-8) + log_softmax fused ----
__global__ void __launch_bounds__(256)
k_agg2(const float* __restrict__ b2, float* __restrict__ out) {
    int warp = (blockIdx.x * blockDim.x + threadIdx.x) >> 5;
    int lane = threadIdx.x & 31;
    if (warp >= NN) return;
    int node = warp;
    int start = g_row[node], end = g_row[node + 1];
    float aldn = g_ald[node];

    float acc0 = 0.f, acc1 = 0.f, den = 0.f;
    for (int base = start; base < end; base += 32) {
        int j = base + lane;
        int sj = (j < end) ? g_srcv[j] : 0;
        float e = __ldg(&g_als[sj]) + aldn;
        e = (e >= 0.f) ? e : 0.2f * e;
        float al = (j < end) ? __expf(e) : 0.f;
#pragma unroll
        for (int k8 = 0; k8 < 4; k8++) {
            if (base + 8 * k8 >= end) break;
            int s[8];
            float w[8];
#pragma unroll
            for (int u = 0; u < 8; u++) {
                s[u] = __shfl_sync(0xffffffffu, sj, 8 * k8 + u);
                w[u] = __shfl_sync(0xffffffffu, al, 8 * k8 + u);
            }
            float h0[8], h1[8];
#pragma unroll
            for (int u = 0; u < 8; u++) {
                const float* hr = &g_h2[(size_t)s[u] * 40];
                h0[u] = hr[lane];
                h1[u] = (lane < 8) ? hr[32 + lane] : 0.f;
            }
#pragma unroll
            for (int u = 0; u < 8; u++) {
                den += w[u];
                acc0 = fmaf(w[u], h0[u], acc0);
                acc1 = fmaf(w[u], h1[u], acc1);
            }
        }
    }
    float invd = 1.f / den;

    float v0 = fmaf(acc0, invd, __ldg(&b2[lane]));
    float v1 = (lane < 8) ? fmaf(acc1, invd, __ldg(&b2[32 + lane])) : -1e30f;
    float mx = fmaxf(v0, v1);
#pragma unroll
    for (int off = 16; off > 0; off >>= 1)
        mx = fmaxf(mx, __shfl_xor_sync(0xffffffffu, mx, off));
    float se = __expf(v0 - mx) + ((lane < 8) ? __expf(v1 - mx) : 0.f);
#pragma unroll
    for (int off = 16; off > 0; off >>= 1)
        se += __shfl_xor_sync(0xffffffffu, se, off);
    float lse = mx + __logf(se);

    out[(size_t)node * 40 + lane] = v0 - lse;
    if (lane < 8) out[(size_t)node * 40 + 32 + lane] = v1 - lse;
}

// ---------------- launch -------------------------------------------------------
extern "C" void kernel_launch(void* const* d_in, const int* in_sizes, int n_in,
                              void* d_out, int out_size) {
    const float* x   = (const float*)d_in[0];
    const void*  ei  = d_in[1];
    const float* W0  = (const float*)d_in[2];
    const float* as0 = (const float*)d_in[3];
    const float* ad0 = (const float*)d_in[4];
    const float* b0  = (const float*)d_in[5];
    const float* W1  = (const float*)d_in[6];
    const float* as1 = (const float*)d_in[7];
    const float* ad1 = (const float*)d_in[8];
    const float* b1  = (const float*)d_in[9];
    const float* W2  = (const float*)d_in[10];
    const float* as2 = (const float*)d_in[11];
    const float* ad2 = (const float*)d_in[12];
    const float* b2  = (const float*)d_in[13];
    float* out = (float*)d_out;

    cudaFuncSetAttribute(k_gemm_mma, cudaFuncAttributeMaxDynamicSharedMemorySize, SMH_TOT);

    // prep (detect + zero + W split) + CSR build
    k_prep<<<(NN + 511) / 512, 512>>>((const int*)ei, W0, W1);
    k_count<<<(ETOT + 511) / 512, 512>>>(ei);
    k_scan1<<<NB, SCAN_B>>>();
    k_scan2<<<1, 128>>>();
    k_scan3<<<(NN + 511) / 512, 512>>>();
    k_fill<<<(ETOT + 511) / 512, 512>>>(ei);

    const int TC_BLKS  = (NN + 127) / 128;        // 391
    const int AGG_BLKS = (NN * 32 + 255) / 256;   // one warp per node

    // layer 0
    k_gemm_mma<<<TC_BLKS, 512, SMH_TOT>>>(x, 0, 0, as0, ad0);
    k_agg<<<AGG_BLKS, 256>>>(b0);

    // layer 1
    k_gemm_mma<<<TC_BLKS, 512, SMH_TOT>>>(nullptr, 1, 1, as1, ad1);
    k_agg<<<AGG_BLKS, 256>>>(b1);

    // layer 2
    k_gemm40<<<(NN + 31) / 32, 256>>>(W2, as2, ad2);
    k_agg2<<<AGG_BLKS, 256>>>(b2, out);
}

// round 9
// speedup vs baseline: 2.1992x; 1.0496x over previous
#include <cuda_runtime.h>
#include <cuda_bf16.h>
#include <cuda_fp16.h>
#include <math.h>
#include <cstdint>

#define NN   50000
#define EE0  800000
#define ETOT 850000
#define NH   4
#define SCAN_B 512
#define NB   ((NN + SCAN_B - 1) / SCAN_B)   // 98

// ---------------- scratch (device globals; no allocation allowed) -------------
__device__ __align__(16) float g_feat[(size_t)NN * 128];
__device__ __align__(16) __half g_h01[(size_t)NN * 128];   // layers 0/1 h (fp16)
__device__ __align__(16) __half g_h2[(size_t)NN * 40];     // layer 2 h (fp16)
__device__ __align__(16) float g_als[NN * NH];
__device__ __align__(16) float g_ald[NN * NH];
__device__ __align__(16) __nv_bfloat16 g_Whi[2][16384];
__device__ __align__(16) __nv_bfloat16 g_Wlo[2][16384];
__device__ int g_deg[NN];
__device__ int g_row[NN + 1];
__device__ int g_cur[NN];
__device__ int g_bsum[NB];
__device__ int g_srcv[ETOT];
__device__ int g_is64;

// ---------------- small helpers -----------------------------------------------
#define MMA_BF16(d, a, b) \
    asm volatile("mma.sync.aligned.m16n8k16.row.col.f32.bf16.bf16.f32 " \
        "{%0,%1,%2,%3}, {%4,%5,%6,%7}, {%8,%9}, {%0,%1,%2,%3};" \
        : "+f"((d)[0]), "+f"((d)[1]), "+f"((d)[2]), "+f"((d)[3]) \
        : "r"((a)[0]), "r"((a)[1]), "r"((a)[2]), "r"((a)[3]), "r"((b)[0]), "r"((b)[1]))

__device__ __forceinline__ void split_bf16(float x, __nv_bfloat16& h, __nv_bfloat16& l) {
    h = __float2bfloat16(x);
    l = __float2bfloat16(x - __bfloat162float(h));
}
__device__ __forceinline__ uint32_t bfpair(__nv_bfloat16 a, __nv_bfloat16 b) {
    return (uint32_t)__bfloat16_as_ushort(a) | ((uint32_t)__bfloat16_as_ushort(b) << 16);
}

// ---------------- edge access --------------------------------------------------
__device__ __forceinline__ void get_edge(const void* ei, int e, int& s, int& d) {
    if (e >= EE0) { s = e - EE0; d = s; return; }
    if (g_is64) {
        const long long* p = (const long long*)ei;
        s = (int)p[e];
        d = (int)p[EE0 + e];
    } else {
        const int* p = (const int*)ei;
        s = p[e];
        d = p[EE0 + e];
    }
}
__device__ __forceinline__ int get_dst(const void* ei, int e) {
    if (e >= EE0) return e - EE0;
    if (g_is64) return (int)((const long long*)ei)[EE0 + e];
    return ((const int*)ei)[EE0 + e];
}

// ------------- prep: dtype detect + deg zero + W hi/lo split (fused) -----------
__global__ void k_prep(const int* __restrict__ ei32,
                       const float* __restrict__ W0, const float* __restrict__ W1) {
    int i = blockIdx.x * blockDim.x + threadIdx.x;
    if (blockIdx.x == 0) {
        __shared__ int zc;
        if (threadIdx.x == 0) zc = 0;
        __syncthreads();
        int z = 0;
        for (int k = threadIdx.x; k < 1024; k += blockDim.x)
            if (ei32[2 * k + 1] == 0) z++;
        atomicAdd(&zc, z);
        __syncthreads();
        if (threadIdx.x == 0) g_is64 = (zc > 512) ? 1 : 0;
    }
    if (i < NN) g_deg[i] = 0;
    if (i < 16384) {
        split_bf16(W0[i], g_Whi[0][i], g_Wlo[0][i]);
    } else if (i < 32768) {
        split_bf16(W1[i - 16384], g_Whi[1][i - 16384], g_Wlo[1][i - 16384]);
    }
}

// ---------------- CSR build ---------------------------------------------------
__global__ void k_count(const void* __restrict__ ei) {
    int e = blockIdx.x * blockDim.x + threadIdx.x;
    if (e >= ETOT) return;
    atomicAdd(&g_deg[get_dst(ei, e)], 1);
}

__global__ void k_scan1() {
    __shared__ int sm[SCAN_B];
    int t = threadIdx.x;
    int idx = blockIdx.x * SCAN_B + t;
    int v = (idx < NN) ? g_deg[idx] : 0;
    sm[t] = v;
    __syncthreads();
#pragma unroll
    for (int off = 1; off < SCAN_B; off <<= 1) {
        int p = (t >= off) ? sm[t - off] : 0;
        __syncthreads();
        sm[t] += p;
        __syncthreads();
    }
    if (idx < NN) g_row[idx] = sm[t] - v;
    if (t == SCAN_B - 1) g_bsum[blockIdx.x] = sm[t];
}

// merged scan2+scan3: each block (512 nodes) computes its own block offset by
// serially summing prior block totals (<=97 independent L2 loads, thread 0),
// then applies it and inits g_cur. One launch instead of two.
__global__ void k_scan23() {
    __shared__ int boff_s;
    int t = threadIdx.x;
    int b = blockIdx.x;
    if (t == 0) {
        int s = 0;
        for (int i = 0; i < b; i++) s += g_bsum[i];
        boff_s = s;
    }
    __syncthreads();
    int idx = b * SCAN_B + t;
    if (idx < NN) {
        int r = g_row[idx] + boff_s;
        g_row[idx] = r;
        g_cur[idx] = r;
    }
    if (idx == 0) g_row[NN] = ETOT;
}

__global__ void k_fill(const void* __restrict__ ei) {
    int e = blockIdx.x * blockDim.x + threadIdx.x;
    if (e >= ETOT) return;
    int s, d;
    get_edge(ei, e, s, d);
    int pos = atomicAdd(&g_cur[d], 1);
    g_srcv[pos] = s;
}

// ======= bf16x3 GEMM via mma.sync (separate hi/lo smem), fused att dots =======
#define SMH_XHI 1024
#define SMH_XLO (SMH_XHI + 128 * 136 * 2)
#define SMH_WHI (SMH_XLO + 128 * 136 * 2)
#define SMH_WLO (SMH_WHI + 128 * 136 * 2)
#define SMH_TOT (SMH_WLO + 128 * 136 * 2)   // 140288

__global__ void __launch_bounds__(512, 1)
k_gemm_mma(const float* __restrict__ xin, int use_gfeat, int widx,
           const float* __restrict__ a_src, const float* __restrict__ a_dst) {
    extern __shared__ char smem[];
    float* AS = (float*)(smem);
    float* AD = (float*)(smem + 512);
    __nv_bfloat16* Xhi = (__nv_bfloat16*)(smem + SMH_XHI);
    __nv_bfloat16* Xlo = (__nv_bfloat16*)(smem + SMH_XLO);
    __nv_bfloat16* Whi = (__nv_bfloat16*)(smem + SMH_WHI);
    __nv_bfloat16* Wlo = (__nv_bfloat16*)(smem + SMH_WLO);
    const float* in = use_gfeat ? g_feat : xin;
    int tid = threadIdx.x;
    int row0 = blockIdx.x * 128;

    if (tid < 128) {
        AS[tid] = a_src[tid];
        AD[tid] = a_dst[tid];
    }
    for (int idx = tid; idx < 128 * 32; idx += 512) {
        int r = idx >> 5, c4 = (idx & 31) * 4;
        int row = row0 + r;
        float4 v = make_float4(0.f, 0.f, 0.f, 0.f);
        if (row < NN) v = *(const float4*)&in[(size_t)row * 128 + c4];
        __nv_bfloat16 h0, h1, h2, h3, l0, l1, l2, l3;
        split_bf16(v.x, h0, l0);
        split_bf16(v.y, h1, l1);
        split_bf16(v.z, h2, l2);
        split_bf16(v.w, h3, l3);
        uint32_t* dh = (uint32_t*)(Xhi + r * 136 + c4);
        uint32_t* dl = (uint32_t*)(Xlo + r * 136 + c4);
        dh[0] = bfpair(h0, h1);
        dh[1] = bfpair(h2, h3);
        dl[0] = bfpair(l0, l1);
        dl[1] = bfpair(l2, l3);
    }
    {
        const __nv_bfloat16* whi = g_Whi[widx];
        const __nv_bfloat16* wlo = g_Wlo[widx];
        for (int idx = tid; idx < 2048; idx += 512) {
            int n = idx >> 4, kc = (idx & 15) * 8;
            *(uint4*)(Whi + n * 136 + kc) = *(const uint4*)(whi + n * 128 + kc);
            *(uint4*)(Wlo + n * 136 + kc) = *(const uint4*)(wlo + n * 128 + kc);
        }
    }
    __syncthreads();

    int w = tid >> 5;
    int lane = tid & 31;
    int g = lane >> 2;
    int tig = lane & 3;
    int rw = (w & 7) * 16;
    int cw = (w >> 3) * 64;

    float acc[8][4];
#pragma unroll
    for (int i = 0; i < 8; i++)
#pragma unroll
        for (int j = 0; j < 4; j++) acc[i][j] = 0.f;

#pragma unroll
    for (int kt = 0; kt < 8; kt++) {
        int kk = kt * 16 + 2 * tig;
        int rA = rw + g, rB = rA + 8;
        uint32_t ahi[4], alo[4];
        ahi[0] = *(const uint32_t*)(Xhi + rA * 136 + kk);
        ahi[1] = *(const uint32_t*)(Xhi + rB * 136 + kk);
        ahi[2] = *(const uint32_t*)(Xhi + rA * 136 + kk + 8);
        ahi[3] = *(const uint32_t*)(Xhi + rB * 136 + kk + 8);
        alo[0] = *(const uint32_t*)(Xlo + rA * 136 + kk);
        alo[1] = *(const uint32_t*)(Xlo + rB * 136 + kk);
        alo[2] = *(const uint32_t*)(Xlo + rA * 136 + kk + 8);
        alo[3] = *(const uint32_t*)(Xlo + rB * 136 + kk + 8);
#pragma unroll
        for (int nt = 0; nt < 8; nt++) {
            int nc = cw + nt * 8 + g;
            uint32_t bhi[2], blo[2];
            bhi[0] = *(const uint32_t*)(Whi + nc * 136 + kk);
            bhi[1] = *(const uint32_t*)(Whi + nc * 136 + kk + 8);
            blo[0] = *(const uint32_t*)(Wlo + nc * 136 + kk);
            blo[1] = *(const uint32_t*)(Wlo + nc * 136 + kk + 8);
            MMA_BF16(acc[nt], ahi, bhi);
            MMA_BF16(acc[nt], ahi, blo);
            MMA_BF16(acc[nt], alo, bhi);
        }
    }

    int rowA = row0 + rw + g;
    int rowB = rowA + 8;
    int h0 = (w >> 3) * 2;
    float ps0[2] = {0.f, 0.f}, ps1[2] = {0.f, 0.f};
    float pd0[2] = {0.f, 0.f}, pd1[2] = {0.f, 0.f};
#pragma unroll
    for (int nt = 0; nt < 8; nt++) {
        int h = nt >> 2;
        int c = cw + nt * 8 + 2 * tig;
        float a0 = AS[c], a1 = AS[c + 1];
        float d0 = AD[c], d1 = AD[c + 1];
        ps0[h] += acc[nt][0] * a0 + acc[nt][1] * a1;
        ps1[h] += acc[nt][2] * a0 + acc[nt][3] * a1;
        pd0[h] += acc[nt][0] * d0 + acc[nt][1] * d1;
        pd1[h] += acc[nt][2] * d0 + acc[nt][3] * d1;
        if (rowA < NN)
            *(__half2*)&g_h01[(size_t)rowA * 128 + c] = __floats2half2_rn(acc[nt][0], acc[nt][1]);
        if (rowB < NN)
            *(__half2*)&g_h01[(size_t)rowB * 128 + c] = __floats2half2_rn(acc[nt][2], acc[nt][3]);
    }
#pragma unroll
    for (int h = 0; h < 2; h++) {
        ps0[h] += __shfl_xor_sync(0xffffffffu, ps0[h], 1);
        ps0[h] += __shfl_xor_sync(0xffffffffu, ps0[h], 2);
        ps1[h] += __shfl_xor_sync(0xffffffffu, ps1[h], 1);
        ps1[h] += __shfl_xor_sync(0xffffffffu, ps1[h], 2);
        pd0[h] += __shfl_xor_sync(0xffffffffu, pd0[h], 1);
        pd0[h] += __shfl_xor_sync(0xffffffffu, pd0[h], 2);
        pd1[h] += __shfl_xor_sync(0xffffffffu, pd1[h], 1);
        pd1[h] += __shfl_xor_sync(0xffffffffu, pd1[h], 2);
    }
    if (tig == 0) {
#pragma unroll
        for (int h = 0; h < 2; h++) {
            if (rowA < NN) {
                g_als[rowA * 4 + h0 + h] = ps0[h];
                g_ald[rowA * 4 + h0 + h] = pd0[h];
            }
            if (rowB < NN) {
                g_als[rowB * 4 + h0 + h] = ps1[h];
                g_ald[rowB * 4 + h0 + h] = pd1[h];
            }
        }
    }
}

// --- single-pass softmax + aggregation, fp16 gather, unrolled-8 (layers 0/1) ---
__global__ void __launch_bounds__(256)
k_agg(const float* __restrict__ bias) {
    int warp = (blockIdx.x * blockDim.x + threadIdx.x) >> 5;
    int lane = threadIdx.x & 31;
    if (warp >= NN) return;
    int node = warp;
    int start = g_row[node], end = g_row[node + 1];

    int head = lane >> 3;
    int sub = lane & 7;
    float aldh = g_ald[node * 4 + head];
    int c4 = lane * 4;
    float4 acc = make_float4(0.f, 0.f, 0.f, 0.f);
    float den = 0.f;

    for (int base = start; base < end; base += 32) {
        int j = base + lane;
        int sj = (j < end) ? g_srcv[j] : 0;
        float er[4];
#pragma unroll
        for (int k = 0; k < 4; k++) {
            int s2 = __shfl_sync(0xffffffffu, sj, sub + 8 * k);
            float e = __ldg(&g_als[s2 * 4 + head]) + aldh;
            e = (e >= 0.f) ? e : 0.2f * e;
            er[k] = (base + sub + 8 * k < end) ? __expf(e) : 0.f;
        }
#pragma unroll
        for (int k8 = 0; k8 < 4; k8++) {
            if (base + 8 * k8 >= end) break;
            float ek = er[k8];
            int s[8];
            float w[8];
#pragma unroll
            for (int u = 0; u < 8; u++) {
                s[u] = __shfl_sync(0xffffffffu, sj, 8 * k8 + u);
                w[u] = __shfl_sync(0xffffffffu, ek, (head << 3) | u);
            }
            uint2 hv[8];
#pragma unroll
            for (int u = 0; u < 8; u++)
                hv[u] = *(const uint2*)(g_h01 + (size_t)s[u] * 128 + c4);
#pragma unroll
            for (int u = 0; u < 8; u++) {
                float2 fa = __half22float2(*reinterpret_cast<__half2*>(&hv[u].x));
                float2 fb = __half22float2(*reinterpret_cast<__half2*>(&hv[u].y));
                den += w[u];
                acc.x = fmaf(w[u], fa.x, acc.x);
                acc.y = fmaf(w[u], fa.y, acc.y);
                acc.z = fmaf(w[u], fb.x, acc.z);
                acc.w = fmaf(w[u], fb.y, acc.w);
            }
        }
    }

    float invd = 1.f / den;
    float4 bv = *(const float4*)&bias[c4];
    float r0 = fmaf(acc.x, invd, bv.x);
    float r1 = fmaf(acc.y, invd, bv.y);
    float r2 = fmaf(acc.z, invd, bv.z);
    float r3 = fmaf(acc.w, invd, bv.w);
    r0 = (r0 > 0.f) ? r0 : expm1f(r0);
    r1 = (r1 > 0.f) ? r1 : expm1f(r1);
    r2 = (r2 > 0.f) ? r2 : expm1f(r2);
    r3 = (r3 > 0.f) ? r3 : expm1f(r3);
    *(float4*)&g_feat[(size_t)node * 128 + c4] = make_float4(r0, r1, r2, r3);
}

// ---------------- layer 2: GEMM (Nout=40) + fused attention dots ---------------
__global__ void __launch_bounds__(256)
k_gemm40(const float* __restrict__ W2,
         const float* __restrict__ a_src2, const float* __restrict__ a_dst2) {
    __shared__ float Wt[128 * 44];
    __shared__ float Xs[32 * 128];
    int t = threadIdx.x;
    int row0 = blockIdx.x * 32;

    for (int idx = t; idx < 40 * 128; idx += 256) {
        int c = idx >> 7, k = idx & 127;
        Wt[k * 44 + c] = W2[idx];
    }
    for (int idx = t; idx < 32 * 32; idx += 256) {
        int r = idx >> 5, c4 = idx & 31;
        int row = row0 + r;
        float4 v = make_float4(0.f, 0.f, 0.f, 0.f);
        if (row < NN) v = *(const float4*)&g_feat[(size_t)row * 128 + c4 * 4];
        *(float4*)&Xs[r * 128 + c4 * 4] = v;
    }

    int cg = t & 7;
    int rg = t >> 3;
    float as[5], ad[5];
#pragma unroll
    for (int j = 0; j < 5; j++) {
        as[j] = __ldg(&a_src2[cg * 5 + j]);
        ad[j] = __ldg(&a_dst2[cg * 5 + j]);
    }
    __syncthreads();

    float acc[5] = {0.f, 0.f, 0.f, 0.f, 0.f};
#pragma unroll 4
    for (int k = 0; k < 128; k++) {
        float a = Xs[rg * 128 + k];
#pragma unroll
        for (int j = 0; j < 5; j++)
            acc[j] = fmaf(a, Wt[k * 44 + cg * 5 + j], acc[j]);
    }

    float ps = 0.f, pd = 0.f;
#pragma unroll
    for (int j = 0; j < 5; j++) {
        ps = fmaf(acc[j], as[j], ps);
        pd = fmaf(acc[j], ad[j], pd);
    }
    ps += __shfl_xor_sync(0xffffffffu, ps, 1);
    ps += __shfl_xor_sync(0xffffffffu, ps, 2);
    ps += __shfl_xor_sync(0xffffffffu, ps, 4);
    pd += __shfl_xor_sync(0xffffffffu, pd, 1);
    pd += __shfl_xor_sync(0xffffffffu, pd, 2);
    pd += __shfl_xor_sync(0xffffffffu, pd, 4);

    int row = row0 + rg;
    if (row < NN) {
#pragma unroll
        for (int j = 0; j < 5; j++)
            g_h2[(size_t)row * 40 + cg * 5 + j] = __float2half(acc[j]);
        if (cg == 0) {
            g_als[row] = ps;
            g_ald[row] = pd;
        }
    }
}

// ---- layer 2: single-pass agg (fp16 gather) + bias + log_softmax fused --------
__global__ void __launch_bounds__(256)
k_agg2(const float* __restrict__ b2, float* __restrict__ out) {
    int warp = (blockIdx.x * blockDim.x + threadIdx.x) >> 5;
    int lane = threadIdx.x & 31;
    if (warp >= NN) return;
    int node = warp;
    int start = g_row[node], end = g_row[node + 1];
    float aldn = g_ald[node];

    float acc0 = 0.f, acc1 = 0.f, den = 0.f;
    for (int base = start; base < end; base += 32) {
        int j = base + lane;
        int sj = (j < end) ? g_srcv[j] : 0;
        float e = __ldg(&g_als[sj]) + aldn;
        e = (e >= 0.f) ? e : 0.2f * e;
        float al = (j < end) ? __expf(e) : 0.f;
#pragma unroll
        for (int k8 = 0; k8 < 4; k8++) {
            if (base + 8 * k8 >= end) break;
            int s[8];
            float w[8];
#pragma unroll
            for (int u = 0; u < 8; u++) {
                s[u] = __shfl_sync(0xffffffffu, sj, 8 * k8 + u);
                w[u] = __shfl_sync(0xffffffffu, al, 8 * k8 + u);
            }
            float h0[8], h1[8];
#pragma unroll
            for (int u = 0; u < 8; u++) {
                const __half* hr = &g_h2[(size_t)s[u] * 40];
                h0[u] = __half2float(hr[lane]);
                h1[u] = (lane < 8) ? __half2float(hr[32 + lane]) : 0.f;
            }
#pragma unroll
            for (int u = 0; u < 8; u++) {
                den += w[u];
                acc0 = fmaf(w[u], h0[u], acc0);
                acc1 = fmaf(w[u], h1[u], acc1);
            }
        }
    }
    float invd = 1.f / den;

    float v0 = fmaf(acc0, invd, __ldg(&b2[lane]));
    float v1 = (lane < 8) ? fmaf(acc1, invd, __ldg(&b2[32 + lane])) : -1e30f;
    float mx = fmaxf(v0, v1);
#pragma unroll
    for (int off = 16; off > 0; off >>= 1)
        mx = fmaxf(mx, __shfl_xor_sync(0xffffffffu, mx, off));
    float se = __expf(v0 - mx) + ((lane < 8) ? __expf(v1 - mx) : 0.f);
#pragma unroll
    for (int off = 16; off > 0; off >>= 1)
        se += __shfl_xor_sync(0xffffffffu, se, off);
    float lse = mx + __logf(se);

    out[(size_t)node * 40 + lane] = v0 - lse;
    if (lane < 8) out[(size_t)node * 40 + 32 + lane] = v1 - lse;
}

// ---------------- launch -------------------------------------------------------
extern "C" void kernel_launch(void* const* d_in, const int* in_sizes, int n_in,
                              void* d_out, int out_size) {
    const float* x   = (const float*)d_in[0];
    const void*  ei  = d_in[1];
    const float* W0  = (const float*)d_in[2];
    const float* as0 = (const float*)d_in[3];
    const float* ad0 = (const float*)d_in[4];
    const float* b0  = (const float*)d_in[5];
    const float* W1  = (const float*)d_in[6];
    const float* as1 = (const float*)d_in[7];
    const float* ad1 = (const float*)d_in[8];
    const float* b1  = (const float*)d_in[9];
    const float* W2  = (const float*)d_in[10];
    const float* as2 = (const float*)d_in[11];
    const float* ad2 = (const float*)d_in[12];
    const float* b2  = (const float*)d_in[13];
    float* out = (float*)d_out;

    // one-time resources (created on the first, non-captured, correctness call)
    static cudaStream_t s2 = nullptr;
    static cudaEvent_t evA = nullptr, evB = nullptr;
    if (s2 == nullptr) {
        cudaStreamCreateWithFlags(&s2, cudaStreamNonBlocking);
        cudaEventCreateWithFlags(&evA, cudaEventDisableTiming);
        cudaEventCreateWithFlags(&evB, cudaEventDisableTiming);
        cudaFuncSetAttribute(k_gemm_mma, cudaFuncAttributeMaxDynamicSharedMemorySize, SMH_TOT);
    }

    const int TC_BLKS  = (NN + 127) / 128;        // 391
    const int AGG_BLKS = (NN * 32 + 255) / 256;   // one warp per node

    // prep (detect + deg zero + W split) on main stream
    k_prep<<<(NN + 511) / 512, 512>>>((const int*)ei, W0, W1);

    // fork: CSR build on s2, overlapped with layer-0 GEMM on main stream
    cudaEventRecord(evA, 0);
    cudaStreamWaitEvent(s2, evA, 0);
    k_count<<<(ETOT + 511) / 512, 512, 0, s2>>>(ei);
    k_scan1<<<NB, SCAN_B, 0, s2>>>();
    k_scan23<<<NB, SCAN_B, 0, s2>>>();
    k_fill<<<(ETOT + 511) / 512, 512, 0, s2>>>(ei);
    cudaEventRecord(evB, s2);

    k_gemm_mma<<<TC_BLKS, 512, SMH_TOT>>>(x, 0, 0, as0, ad0);

    // join: aggregation needs both CSR and h
    cudaStreamWaitEvent(0, evB, 0);
    k_agg<<<AGG_BLKS, 256>>>(b0);

    // layer 1
    k_gemm_mma<<<TC_BLKS, 512, SMH_TOT>>>(nullptr, 1, 1, as1, ad1);
    k_agg<<<AGG_BLKS, 256>>>(b1);

    // layer 2
    k_gemm40<<<(NN + 31) / 32, 256>>>(W2, as2, ad2);
    k_agg2<<<AGG_BLKS, 256>>>(b2, out);
}

// round 12
// speedup vs baseline: 2.2397x; 1.0184x over previous
#include <cuda_runtime.h>
#include <cuda_bf16.h>
#include <cuda_fp16.h>
#include <math.h>
#include <cstdint>

#define NN   50000
#define EE0  800000
#define ETOT 850000
#define NH   4
#define SCAN_B 512
#define NB   ((NN + SCAN_B - 1) / SCAN_B)   // 98

// ---------------- scratch (device globals; no allocation allowed) -------------
__device__ __align__(16) __half g_feat[(size_t)NN * 128];  // inter-layer feats (fp16)
__device__ __align__(16) __half g_h01[(size_t)NN * 128];   // layers 0/1 h (fp16)
__device__ __align__(16) __half g_h2[(size_t)NN * 40];     // layer 2 h (fp16)
__device__ __align__(16) float g_als[NN * NH];
__device__ __align__(16) float g_ald[NN * NH];
__device__ __align__(16) __nv_bfloat16 g_Whi[2][16384];
__device__ __align__(16) __nv_bfloat16 g_Wlo[2][16384];
__device__ int g_deg[NN];
__device__ int g_row[NN + 1];
__device__ int g_cur[NN];
__device__ int g_bsum[NB];
__device__ int g_srcv[ETOT];
__device__ int g_is64;

// ---------------- small helpers -----------------------------------------------
#define MMA_BF16(d, a, b) \
    asm volatile("mma.sync.aligned.m16n8k16.row.col.f32.bf16.bf16.f32 " \
        "{%0,%1,%2,%3}, {%4,%5,%6,%7}, {%8,%9}, {%0,%1,%2,%3};" \
        : "+f"((d)[0]), "+f"((d)[1]), "+f"((d)[2]), "+f"((d)[3]) \
        : "r"((a)[0]), "r"((a)[1]), "r"((a)[2]), "r"((a)[3]), "r"((b)[0]), "r"((b)[1]))

__device__ __forceinline__ void split_bf16(float x, __nv_bfloat16& h, __nv_bfloat16& l) {
    h = __float2bfloat16(x);
    l = __float2bfloat16(x - __bfloat162float(h));
}
__device__ __forceinline__ uint32_t bfpair(__nv_bfloat16 a, __nv_bfloat16 b) {
    return (uint32_t)__bfloat16_as_ushort(a) | ((uint32_t)__bfloat16_as_ushort(b) << 16);
}

// ---------------- edge access --------------------------------------------------
__device__ __forceinline__ void get_edge(const void* ei, int e, int& s, int& d) {
    if (e >= EE0) { s = e - EE0; d = s; return; }
    if (g_is64) {
        const long long* p = (const long long*)ei;
        s = (int)p[e];
        d = (int)p[EE0 + e];
    } else {
        const int* p = (const int*)ei;
        s = p[e];
        d = p[EE0 + e];
    }
}
__device__ __forceinline__ int get_dst(const void* ei, int e) {
    if (e >= EE0) return e - EE0;
    if (g_is64) return (int)((const long long*)ei)[EE0 + e];
    return ((const int*)ei)[EE0 + e];
}

// ---------------- init: dtype detect + deg zero (CSR prerequisites only) -------
__global__ void k_init(const int* __restrict__ ei32) {
    int i = blockIdx.x * blockDim.x + threadIdx.x;
    if (blockIdx.x == 0) {
        __shared__ int zc;
        if (threadIdx.x == 0) zc = 0;
        __syncthreads();
        int z = 0;
        for (int k = threadIdx.x; k < 1024; k += blockDim.x)
            if (ei32[2 * k + 1] == 0) z++;
        atomicAdd(&zc, z);
        __syncthreads();
        if (threadIdx.x == 0) g_is64 = (zc > 512) ? 1 : 0;
    }
    if (i < NN) g_deg[i] = 0;
}

// ---------------- W split (needed only by GEMMs) -------------------------------
__global__ void k_wsplit(const float* __restrict__ W0, const float* __restrict__ W1) {
    int i = blockIdx.x * blockDim.x + threadIdx.x;
    if (i < 16384) {
        split_bf16(W0[i], g_Whi[0][i], g_Wlo[0][i]);
    } else if (i < 32768) {
        split_bf16(W1[i - 16384], g_Whi[1][i - 16384], g_Wlo[1][i - 16384]);
    }
}

// ---------------- CSR build ---------------------------------------------------
__global__ void k_count(const void* __restrict__ ei) {
    int e = blockIdx.x * blockDim.x + threadIdx.x;
    if (e >= ETOT) return;
    atomicAdd(&g_deg[get_dst(ei, e)], 1);
}

__global__ void k_scan1() {
    __shared__ int sm[SCAN_B];
    int t = threadIdx.x;
    int idx = blockIdx.x * SCAN_B + t;
    int v = (idx < NN) ? g_deg[idx] : 0;
    sm[t] = v;
    __syncthreads();
#pragma unroll
    for (int off = 1; off < SCAN_B; off <<= 1) {
        int p = (t >= off) ? sm[t - off] : 0;
        __syncthreads();
        sm[t] += p;
        __syncthreads();
    }
    if (idx < NN) g_row[idx] = sm[t] - v;
    if (t == SCAN_B - 1) g_bsum[blockIdx.x] = sm[t];
}

// merged scan2+scan3: every block does a parallel 128-wide scan of the 98 block
// totals (cheap, redundant) and takes its exclusive prefix; then applies it.
__global__ void k_scan23() {
    __shared__ int sm[128];
    int t = threadIdx.x;
    int b = blockIdx.x;
    if (t < 128) {
        sm[t] = (t < NB) ? g_bsum[t] : 0;
    }
    __syncthreads();
#pragma unroll
    for (int off = 1; off < 128; off <<= 1) {
        int p = 0;
        if (t < 128 && t >= off) p = sm[t - off];
        __syncthreads();
        if (t < 128) sm[t] += p;
        __syncthreads();
    }
    int boff = (b > 0) ? sm[b - 1] : 0;   // exclusive prefix of this block
    int idx = b * SCAN_B + t;
    if (idx < NN) {
        int r = g_row[idx] + boff;
        g_row[idx] = r;
        g_cur[idx] = r;
    }
    if (idx == 0) g_row[NN] = ETOT;
}

__global__ void k_fill(const void* __restrict__ ei) {
    int e = blockIdx.x * blockDim.x + threadIdx.x;
    if (e >= ETOT) return;
    int s, d;
    get_edge(ei, e, s, d);
    int pos = atomicAdd(&g_cur[d], 1);
    g_srcv[pos] = s;
}

// ======= bf16x3 GEMM via mma.sync (separate hi/lo smem), fused att dots =======
#define SMH_XHI 1024
#define SMH_XLO (SMH_XHI + 128 * 136 * 2)
#define SMH_WHI (SMH_XLO + 128 * 136 * 2)
#define SMH_WLO (SMH_WHI + 128 * 136 * 2)
#define SMH_TOT (SMH_WLO + 128 * 136 * 2)   // 140288

__global__ void __launch_bounds__(512, 1)
k_gemm_mma(const float* __restrict__ xin, int use_gfeat, int widx,
           const float* __restrict__ a_src, const float* __restrict__ a_dst) {
    extern __shared__ char smem[];
    float* AS = (float*)(smem);
    float* AD = (float*)(smem + 512);
    __nv_bfloat16* Xhi = (__nv_bfloat16*)(smem + SMH_XHI);
    __nv_bfloat16* Xlo = (__nv_bfloat16*)(smem + SMH_XLO);
    __nv_bfloat16* Whi = (__nv_bfloat16*)(smem + SMH_WHI);
    __nv_bfloat16* Wlo = (__nv_bfloat16*)(smem + SMH_WLO);
    int tid = threadIdx.x;
    int row0 = blockIdx.x * 128;

    if (tid < 128) {
        AS[tid] = a_src[tid];
        AD[tid] = a_dst[tid];
    }
    // stage X: (fp32 input | fp16 g_feat) -> bf16 hi/lo in separate arrays
    for (int idx = tid; idx < 128 * 32; idx += 512) {
        int r = idx >> 5, c4 = (idx & 31) * 4;
        int row = row0 + r;
        float4 v = make_float4(0.f, 0.f, 0.f, 0.f);
        if (row < NN) {
            if (use_gfeat) {
                uint2 hv = *(const uint2*)(g_feat + (size_t)row * 128 + c4);
                float2 fa = __half22float2(*reinterpret_cast<__half2*>(&hv.x));
                float2 fb = __half22float2(*reinterpret_cast<__half2*>(&hv.y));
                v = make_float4(fa.x, fa.y, fb.x, fb.y);
            } else {
                v = *(const float4*)&xin[(size_t)row * 128 + c4];
            }
        }
        __nv_bfloat16 h0, h1, h2, h3, l0, l1, l2, l3;
        split_bf16(v.x, h0, l0);
        split_bf16(v.y, h1, l1);
        split_bf16(v.z, h2, l2);
        split_bf16(v.w, h3, l3);
        uint32_t* dh = (uint32_t*)(Xhi + r * 136 + c4);
        uint32_t* dl = (uint32_t*)(Xlo + r * 136 + c4);
        dh[0] = bfpair(h0, h1);
        dh[1] = bfpair(h2, h3);
        dl[0] = bfpair(l0, l1);
        dl[1] = bfpair(l2, l3);
    }
    {
        const __nv_bfloat16* whi = g_Whi[widx];
        const __nv_bfloat16* wlo = g_Wlo[widx];
        for (int idx = tid; idx < 2048; idx += 512) {
            int n = idx >> 4, kc = (idx & 15) * 8;
            *(uint4*)(Whi + n * 136 + kc) = *(const uint4*)(whi + n * 128 + kc);
            *(uint4*)(Wlo + n * 136 + kc) = *(const uint4*)(wlo + n * 128 + kc);
        }
    }
    __syncthreads();

    int w = tid >> 5;
    int lane = tid & 31;
    int g = lane >> 2;
    int tig = lane & 3;
    int rw = (w & 7) * 16;
    int cw = (w >> 3) * 64;

    float acc[8][4];
#pragma unroll
    for (int i = 0; i < 8; i++)
#pragma unroll
        for (int j = 0; j < 4; j++) acc[i][j] = 0.f;

#pragma unroll
    for (int kt = 0; kt < 8; kt++) {
        int kk = kt * 16 + 2 * tig;
        int rA = rw + g, rB = rA + 8;
        uint32_t ahi[4], alo[4];
        ahi[0] = *(const uint32_t*)(Xhi + rA * 136 + kk);
        ahi[1] = *(const uint32_t*)(Xhi + rB * 136 + kk);
        ahi[2] = *(const uint32_t*)(Xhi + rA * 136 + kk + 8);
        ahi[3] = *(const uint32_t*)(Xhi + rB * 136 + kk + 8);
        alo[0] = *(const uint32_t*)(Xlo + rA * 136 + kk);
        alo[1] = *(const uint32_t*)(Xlo + rB * 136 + kk);
        alo[2] = *(const uint32_t*)(Xlo + rA * 136 + kk + 8);
        alo[3] = *(const uint32_t*)(Xlo + rB * 136 + kk + 8);
#pragma unroll
        for (int nt = 0; nt < 8; nt++) {
            int nc = cw + nt * 8 + g;
            uint32_t bhi[2], blo[2];
            bhi[0] = *(const uint32_t*)(Whi + nc * 136 + kk);
            bhi[1] = *(const uint32_t*)(Whi + nc * 136 + kk + 8);
            blo[0] = *(const uint32_t*)(Wlo + nc * 136 + kk);
            blo[1] = *(const uint32_t*)(Wlo + nc * 136 + kk + 8);
            MMA_BF16(acc[nt], ahi, bhi);
            MMA_BF16(acc[nt], ahi, blo);
            MMA_BF16(acc[nt], alo, bhi);
        }
    }

    int rowA = row0 + rw + g;
    int rowB = rowA + 8;
    int h0 = (w >> 3) * 2;
    float ps0[2] = {0.f, 0.f}, ps1[2] = {0.f, 0.f};
    float pd0[2] = {0.f, 0.f}, pd1[2] = {0.f, 0.f};
#pragma unroll
    for (int nt = 0; nt < 8; nt++) {
        int h = nt >> 2;
        int c = cw + nt * 8 + 2 * tig;
        float a0 = AS[c], a1 = AS[c + 1];
        float d0 = AD[c], d1 = AD[c + 1];
        ps0[h] += acc[nt][0] * a0 + acc[nt][1] * a1;
        ps1[h] += acc[nt][2] * a0 + acc[nt][3] * a1;
        pd0[h] += acc[nt][0] * d0 + acc[nt][1] * d1;
        pd1[h] += acc[nt][2] * d0 + acc[nt][3] * d1;
        if (rowA < NN)
            *(__half2*)&g_h01[(size_t)rowA * 128 + c] = __floats2half2_rn(acc[nt][0], acc[nt][1]);
        if (rowB < NN)
            *(__half2*)&g_h01[(size_t)rowB * 128 + c] = __floats2half2_rn(acc[nt][2], acc[nt][3]);
    }
#pragma unroll
    for (int h = 0; h < 2; h++) {
        ps0[h] += __shfl_xor_sync(0xffffffffu, ps0[h], 1);
        ps0[h] += __shfl_xor_sync(0xffffffffu, ps0[h], 2);
        ps1[h] += __shfl_xor_sync(0xffffffffu, ps1[h], 1);
        ps1[h] += __shfl_xor_sync(0xffffffffu, ps1[h], 2);
        pd0[h] += __shfl_xor_sync(0xffffffffu, pd0[h], 1);
        pd0[h] += __shfl_xor_sync(0xffffffffu, pd0[h], 2);
        pd1[h] += __shfl_xor_sync(0xffffffffu, pd1[h], 1);
        pd1[h] += __shfl_xor_sync(0xffffffffu, pd1[h], 2);
    }
    if (tig == 0) {
#pragma unroll
        for (int h = 0; h < 2; h++) {
            if (rowA < NN) {
                g_als[rowA * 4 + h0 + h] = ps0[h];
                g_ald[rowA * 4 + h0 + h] = pd0[h];
            }
            if (rowB < NN) {
                g_als[rowB * 4 + h0 + h] = ps1[h];
                g_ald[rowB * 4 + h0 + h] = pd1[h];
            }
        }
    }
}

// --- single-pass softmax + aggregation, fp16 gather, unrolled-8 (layers 0/1) ---
__global__ void __launch_bounds__(256)
k_agg(const float* __restrict__ bias) {
    int warp = (blockIdx.x * blockDim.x + threadIdx.x) >> 5;
    int lane = threadIdx.x & 31;
    if (warp >= NN) return;
    int node = warp;
    int start = g_row[node], end = g_row[node + 1];

    int head = lane >> 3;
    int sub = lane & 7;
    float aldh = g_ald[node * 4 + head];
    int c4 = lane * 4;
    float4 acc = make_float4(0.f, 0.f, 0.f, 0.f);
    float den = 0.f;

    for (int base = start; base < end; base += 32) {
        int j = base + lane;
        int sj = (j < end) ? g_srcv[j] : 0;
        float er[4];
#pragma unroll
        for (int k = 0; k < 4; k++) {
            int s2 = __shfl_sync(0xffffffffu, sj, sub + 8 * k);
            float e = __ldg(&g_als[s2 * 4 + head]) + aldh;
            e = (e >= 0.f) ? e : 0.2f * e;
            er[k] = (base + sub + 8 * k < end) ? __expf(e) : 0.f;
        }
#pragma unroll
        for (int k8 = 0; k8 < 4; k8++) {
            if (base + 8 * k8 >= end) break;
            float ek = er[k8];
            int s[8];
            float w[8];
#pragma unroll
            for (int u = 0; u < 8; u++) {
                s[u] = __shfl_sync(0xffffffffu, sj, 8 * k8 + u);
                w[u] = __shfl_sync(0xffffffffu, ek, (head << 3) | u);
            }
            uint2 hv[8];
#pragma unroll
            for (int u = 0; u < 8; u++)
                hv[u] = *(const uint2*)(g_h01 + (size_t)s[u] * 128 + c4);
#pragma unroll
            for (int u = 0; u < 8; u++) {
                float2 fa = __half22float2(*reinterpret_cast<__half2*>(&hv[u].x));
                float2 fb = __half22float2(*reinterpret_cast<__half2*>(&hv[u].y));
                den += w[u];
                acc.x = fmaf(w[u], fa.x, acc.x);
                acc.y = fmaf(w[u], fa.y, acc.y);
                acc.z = fmaf(w[u], fb.x, acc.z);
                acc.w = fmaf(w[u], fb.y, acc.w);
            }
        }
    }

    float invd = 1.f / den;
    float4 bv = *(const float4*)&bias[c4];
    float r0 = fmaf(acc.x, invd, bv.x);
    float r1 = fmaf(acc.y, invd, bv.y);
    float r2 = fmaf(acc.z, invd, bv.z);
    float r3 = fmaf(acc.w, invd, bv.w);
    r0 = (r0 > 0.f) ? r0 : expm1f(r0);
    r1 = (r1 > 0.f) ? r1 : expm1f(r1);
    r2 = (r2 > 0.f) ? r2 : expm1f(r2);
    r3 = (r3 > 0.f) ? r3 : expm1f(r3);
    uint2 o;
    *reinterpret_cast<__half2*>(&o.x) = __floats2half2_rn(r0, r1);
    *reinterpret_cast<__half2*>(&o.y) = __floats2half2_rn(r2, r3);
    *(uint2*)(g_feat + (size_t)node * 128 + c4) = o;
}

// ---------------- layer 2: GEMM (Nout=40) + fused attention dots ---------------
__global__ void __launch_bounds__(256)
k_gemm40(const float* __restrict__ W2,
         const float* __restrict__ a_src2, const float* __restrict__ a_dst2) {
    __shared__ float Wt[128 * 44];
    __shared__ float Xs[32 * 128];
    int t = threadIdx.x;
    int row0 = blockIdx.x * 32;

    for (int idx = t; idx < 40 * 128; idx += 256) {
        int c = idx >> 7, k = idx & 127;
        Wt[k * 44 + c] = W2[idx];
    }
    for (int idx = t; idx < 32 * 32; idx += 256) {
        int r = idx >> 5, c4 = (idx & 31) * 4;
        int row = row0 + r;
        float4 v = make_float4(0.f, 0.f, 0.f, 0.f);
        if (row < NN) {
            uint2 hv = *(const uint2*)(g_feat + (size_t)row * 128 + c4);
            float2 fa = __half22float2(*reinterpret_cast<__half2*>(&hv.x));
            float2 fb = __half22float2(*reinterpret_cast<__half2*>(&hv.y));
            v = make_float4(fa.x, fa.y, fb.x, fb.y);
        }
        *(float4*)&Xs[r * 128 + c4] = v;
    }

    int cg = t & 7;
    int rg = t >> 3;
    float as[5], ad[5];
#pragma unroll
    for (int j = 0; j < 5; j++) {
        as[j] = __ldg(&a_src2[cg * 5 + j]);
        ad[j] = __ldg(&a_dst2[cg * 5 + j]);
    }
    __syncthreads();

    float acc[5] = {0.f, 0.f, 0.f, 0.f, 0.f};
#pragma unroll 4
    for (int k = 0; k < 128; k++) {
        float a = Xs[rg * 128 + k];
#pragma unroll
        for (int j = 0; j < 5; j++)
            acc[j] = fmaf(a, Wt[k * 44 + cg * 5 + j], acc[j]);
    }

    float ps = 0.f, pd = 0.f;
#pragma unroll
    for (int j = 0; j < 5; j++) {
        ps = fmaf(acc[j], as[j], ps);
        pd = fmaf(acc[j], ad[j], pd);
    }
    ps += __shfl_xor_sync(0xffffffffu, ps, 1);
    ps += __shfl_xor_sync(0xffffffffu, ps, 2);
    ps += __shfl_xor_sync(0xffffffffu, ps, 4);
    pd += __shfl_xor_sync(0xffffffffu, pd, 1);
    pd += __shfl_xor_sync(0xffffffffu, pd, 2);
    pd += __shfl_xor_sync(0xffffffffu, pd, 4);

    int row = row0 + rg;
    if (row < NN) {
#pragma unroll
        for (int j = 0; j < 5; j++)
            g_h2[(size_t)row * 40 + cg * 5 + j] = __float2half(acc[j]);
        if (cg == 0) {
            g_als[row] = ps;
            g_ald[row] = pd;
        }
    }
}

// ---- layer 2: single-pass agg (fp16 gather) + bias + log_softmax fused --------
__global__ void __launch_bounds__(256)
k_agg2(const float* __restrict__ b2, float* __restrict__ out) {
    int warp = (blockIdx.x * blockDim.x + threadIdx.x) >> 5;
    int lane = threadIdx.x & 31;
    if (warp >= NN) return;
    int node = warp;
    int start = g_row[node], end = g_row[node + 1];
    float aldn = g_ald[node];

    float acc0 = 0.f, acc1 = 0.f, den = 0.f;
    for (int base = start; base < end; base += 32) {
        int j = base + lane;
        int sj = (j < end) ? g_srcv[j] : 0;
        float e = __ldg(&g_als[sj]) + aldn;
        e = (e >= 0.f) ? e : 0.2f * e;
        float al = (j < end) ? __expf(e) : 0.f;
#pragma unroll
        for (int k8 = 0; k8 < 4; k8++) {
            if (base + 8 * k8 >= end) break;
            int s[8];
            float w[8];
#pragma unroll
            for (int u = 0; u < 8; u++) {
                s[u] = __shfl_sync(0xffffffffu, sj, 8 * k8 + u);
                w[u] = __shfl_sync(0xffffffffu, al, 8 * k8 + u);
            }
            float h0[8], h1[8];
#pragma unroll
            for (int u = 0; u < 8; u++) {
                const __half* hr = &g_h2[(size_t)s[u] * 40];
                h0[u] = __half2float(hr[lane]);
                h1[u] = (lane < 8) ? __half2float(hr[32 + lane]) : 0.f;
            }
#pragma unroll
            for (int u = 0; u < 8; u++) {
                den += w[u];
                acc0 = fmaf(w[u], h0[u], acc0);
                acc1 = fmaf(w[u], h1[u], acc1);
            }
        }
    }
    float invd = 1.f / den;

    float v0 = fmaf(acc0, invd, __ldg(&b2[lane]));
    float v1 = (lane < 8) ? fmaf(acc1, invd, __ldg(&b2[32 + lane])) : -1e30f;
    float mx = fmaxf(v0, v1);
#pragma unroll
    for (int off = 16; off > 0; off >>= 1)
        mx = fmaxf(mx, __shfl_xor_sync(0xffffffffu, mx, off));
    float se = __expf(v0 - mx) + ((lane < 8) ? __expf(v1 - mx) : 0.f);
#pragma unroll
    for (int off = 16; off > 0; off >>= 1)
        se += __shfl_xor_sync(0xffffffffu, se, off);
    float lse = mx + __logf(se);

    out[(size_t)node * 40 + lane] = v0 - lse;
    if (lane < 8) out[(size_t)node * 40 + 32 + lane] = v1 - lse;
}

// ---------------- launch -------------------------------------------------------
extern "C" void kernel_launch(void* const* d_in, const int* in_sizes, int n_in,
                              void* d_out, int out_size) {
    const float* x   = (const float*)d_in[0];
    const void*  ei  = d_in[1];
    const float* W0  = (const float*)d_in[2];
    const float* as0 = (const float*)d_in[3];
    const float* ad0 = (const float*)d_in[4];
    const float* b0  = (const float*)d_in[5];
    const float* W1  = (const float*)d_in[6];
    const float* as1 = (const float*)d_in[7];
    const float* ad1 = (const float*)d_in[8];
    const float* b1  = (const float*)d_in[9];
    const float* W2  = (const float*)d_in[10];
    const float* as2 = (const float*)d_in[11];
    const float* ad2 = (const float*)d_in[12];
    const float* b2  = (const float*)d_in[13];
    float* out = (float*)d_out;

    static cudaStream_t s2 = nullptr;
    static cudaEvent_t evA = nullptr, evB = nullptr;
    if (s2 == nullptr) {
        cudaStreamCreateWithFlags(&s2, cudaStreamNonBlocking);
        cudaEventCreateWithFlags(&evA, cudaEventDisableTiming);
        cudaEventCreateWithFlags(&evB, cudaEventDisableTiming);
        cudaFuncSetAttribute(k_gemm_mma, cudaFuncAttributeMaxDynamicSharedMemorySize, SMH_TOT);
    }

    const int TC_BLKS  = (NN + 127) / 128;        // 391
    const int AGG_BLKS = (NN * 32 + 255) / 256;   // one warp per node

    // init (detect + deg zero) — the only CSR prerequisites
    k_init<<<(NN + 511) / 512, 512>>>((const int*)ei);

    // fork: CSR build on s2, overlapped with W split + layer-0 GEMM on main
    cudaEventRecord(evA, 0);
    cudaStreamWaitEvent(s2, evA, 0);
    k_count<<<(ETOT + 511) / 512, 512, 0, s2>>>(ei);
    k_scan1<<<NB, SCAN_B, 0, s2>>>();
    k_scan23<<<NB, SCAN_B, 0, s2>>>();
    k_fill<<<(ETOT + 511) / 512, 512, 0, s2>>>(ei);
    cudaEventRecord(evB, s2);

    k_wsplit<<<(32768 + 511) / 512, 512>>>(W0, W1);
    k_gemm_mma<<<TC_BLKS, 512, SMH_TOT>>>(x, 0, 0, as0, ad0);

    // join: aggregation needs both CSR and h
    cudaStreamWaitEvent(0, evB, 0);
    k_agg<<<AGG_BLKS, 256>>>(b0);

    // layer 1
    k_gemm_mma<<<TC_BLKS, 512, SMH_TOT>>>(nullptr, 1, 1, as1, ad1);
    k_agg<<<AGG_BLKS, 256>>>(b1);

    // layer 2
    k_gemm40<<<(NN + 31) / 32, 256>>>(W2, as2, ad2);
    k_agg2<<<AGG_BLKS, 256>>>(b2, out);
}